// round 13
// baseline (speedup 1.0000x reference)
#include <cuda_runtime.h>
#include <cuda_bf16.h>
#include <cuda_fp16.h>
#include <math.h>

#define NG 20000
#define NP 100000
#define NM 5000
#define NTOT (NG + NP + NM)
#define HID 64
#define EMAX 1000000
#define FULL 0xFFFFFFFFu

// live edge types (orig ids): 0: gene->patient, 1: patient->gene, 2(orig 3): group->gene
// segment layout for agg: e0 | e1 | e3
#define A0 0
#define A1 NP
#define A3 (NP + NG)
#define NSEG1 (NP + 2 * NG)          // layer-1 pull covers all three
// tiles for the fused linear
#define T0 ((NP + 63) / 64)          // patient tiles
#define T1 ((NG + 63) / 64)          // gene mega-tiles
// scan chunking
#define SCH 1024
#define NB0 ((NP + SCH - 1) / SCH)   // 98
#define NB1 ((NG + SCH - 1) / SCH)   // 20
#define NB3 NB1                      // 20
#define NBTOT (NB0 + NB1 + NB3)      // 138

// ---------------- scratch (static device globals; no allocs) ----------------
__device__ float  g_h  [NTOT * HID];               // fp32 master [gene|patient|group]
__device__ __align__(16) __half g_h16[NTOT * HID]; // fp16 gather mirror
__device__ float  g_agg[NSEG1 * HID];
__device__ int    g_cnt[3][NP];      // zero at load; scanC restores zeros each call
__device__ int    g_off[3][NP + 1];
__device__ int    g_cur[3][NP + 1];
__device__ int    g_col[3][EMAX];
__device__ int    g_part[NBTOT];

#define OFF_GENE 0
#define OFF_PAT  (NG * HID)
#define OFF_GRP  ((NG + NP) * HID)

__device__ __forceinline__ float elu1(float x) { return x > 0.f ? x : expm1f(x); }

__constant__ int c_Ns[3] = { NP, NG, NG };

__device__ __forceinline__ void decode_scan_block(int b, int& t, int& c) {
    if      (b < NB0)       { t = 0; c = b; }
    else if (b < NB0 + NB1) { t = 1; c = b - NB0; }
    else                    { t = 2; c = b - NB0 - NB1; }
}

// ---------------- merged encoder: all 3 node types in one launch ----------------
__global__ void enc_all_kernel(const float* __restrict__ x_gene,
                               const float* __restrict__ x_pat,
                               const float* __restrict__ x_grp,
                               const float* __restrict__ Wg, const float* __restrict__ bg,
                               const float* __restrict__ Wp, const float* __restrict__ bp,
                               const float* __restrict__ Wm, const float* __restrict__ bm,
                               float* __restrict__ h, __half* __restrict__ h16) {
    int idx = blockIdx.x * blockDim.x + threadIdx.x;
    if (idx >= NTOT * HID) return;
    int n = idx >> 6;
    int j = idx & 63;
    const float* x; const float* W; const float* b; int K; int row; bool wf32;
    if (n < NG)           { x = x_gene; W = Wg; b = bg; K = 11; row = n;            wf32 = true; }
    else if (n < NG + NP) { x = x_pat;  W = Wp; b = bp; K = 3;  row = n - NG;       wf32 = true; }
    else                  { x = x_grp;  W = Wm; b = bm; K = 4;  row = n - NG - NP;  wf32 = false; }
    float acc = b[j];
    for (int k = 0; k < K; k++)
        acc += x[row * K + k] * W[k * HID + j];
    float y = elu1(acc);
    if (wf32) h[idx] = y;
    h16[idx] = __float2half(y);
}

// ---------------- CSR build (3 live edge types) ----------------
__global__ void count_all_kernel(const int* __restrict__ d0, const int* __restrict__ d1,
                                 const int* __restrict__ d3, int E) {
    int i = blockIdx.x * blockDim.x + threadIdx.x;
    if (i >= 3 * E) return;
    int t = (i >= E) + (i >= 2 * E);
    int j = i - t * E;
    const int* d = (t == 0) ? d0 : (t == 1) ? d1 : d3;
    atomicAdd(&g_cnt[t][d[j]], 1);
}

__global__ void scanA_kernel() {
    int t, c;
    decode_scan_block(blockIdx.x, t, c);
    int N = c_Ns[t];
    const int* cnt = g_cnt[t];
    int base = c * SCH + threadIdx.x * 4;
    int s = 0;
#pragma unroll
    for (int k = 0; k < 4; k++) {
        int i = base + k;
        if (i < N) s += cnt[i];
    }
    __shared__ int wsum[8];
    int lane = threadIdx.x & 31, wid = threadIdx.x >> 5;
#pragma unroll
    for (int o = 16; o; o >>= 1) s += __shfl_xor_sync(FULL, s, o);
    if (lane == 0) wsum[wid] = s;
    __syncthreads();
    if (threadIdx.x == 0) {
        int tot = 0;
#pragma unroll
        for (int w = 0; w < 8; w++) tot += wsum[w];
        g_part[blockIdx.x] = tot;
    }
}

// scanC (folded scanB): per-chunk exclusive scan; carry from predecessor partials;
// writes off AND cur; resets cnt to zero (invariant restore).
__global__ void scanC_kernel(int E) {
    int t, c;
    decode_scan_block(blockIdx.x, t, c);
    int N = c_Ns[t];
    int* cnt = g_cnt[t];
    int* off = g_off[t];
    int* cur = g_cur[t];

    __shared__ int s_carry;
    int lane = threadIdx.x & 31, wid = threadIdx.x >> 5;
    if (wid == 0) {
        int pb = (t == 0) ? 0 : (t == 1) ? NB0 : NB0 + NB1;
        int sum = 0;
        for (int i = lane; i < c; i += 32) sum += g_part[pb + i];
#pragma unroll
        for (int o = 16; o; o >>= 1) sum += __shfl_xor_sync(FULL, sum, o);
        if (lane == 0) s_carry = sum;
    }
    __syncthreads();
    int carry = s_carry;

    int base = c * SCH + threadIdx.x * 4;
    int v[4];
    int tsum = 0;
#pragma unroll
    for (int k = 0; k < 4; k++) {
        int i = base + k;
        v[k] = (i < N) ? cnt[i] : 0;
        tsum += v[k];
    }
    __shared__ int wsum[8];
    int x = tsum;
#pragma unroll
    for (int o = 1; o < 32; o <<= 1) { int tt = __shfl_up_sync(FULL, x, o); if (lane >= o) x += tt; }
    if (lane == 31) wsum[wid] = x;
    __syncthreads();
    if (wid == 0 && lane < 8) {
        int w = wsum[lane];
#pragma unroll
        for (int o = 1; o < 8; o <<= 1) { int tt = __shfl_up_sync(0xFFu, w, o); if (lane >= o) w += tt; }
        wsum[lane] = w;
    }
    __syncthreads();
    int excl = (x - tsum) + (wid > 0 ? wsum[wid - 1] : 0) + carry;
#pragma unroll
    for (int k = 0; k < 4; k++) {
        int i = base + k;
        if (i < N) { off[i] = excl; cur[i] = excl; cnt[i] = 0; }
        excl += v[k];
    }
    if (threadIdx.x == 0 && c == (N + SCH - 1) / SCH - 1) off[N] = E;
}

__global__ void fill_all_kernel(const int* __restrict__ s0, const int* __restrict__ d0,
                                const int* __restrict__ s1, const int* __restrict__ d1,
                                const int* __restrict__ s3, const int* __restrict__ d3,
                                int E) {
    int i = blockIdx.x * blockDim.x + threadIdx.x;
    if (i >= 3 * E) return;
    int t = (i >= E) + (i >= 2 * E);
    int j = i - t * E;
    const int* s = (t == 0) ? s0 : (t == 1) ? s1 : s3;
    const int* d = (t == 0) ? d0 : (t == 1) ? d1 : d3;
    int p = atomicAdd(&g_cur[t][d[j]], 1);
    g_col[t][p] = s[j];
}

// ---------------- pull aggregation (mean), fp16 gather ----------------
__global__ void pull_all_kernel(const __half* __restrict__ h16buf,
                                float* __restrict__ agg, int nseg) {
    int warp = (blockIdx.x * blockDim.x + threadIdx.x) >> 5;
    int lane = threadIdx.x & 31;
    if (warp >= nseg) return;

    int t, n;
    if      (warp < A1) { t = 0; n = warp; }
    else if (warp < A3) { t = 1; n = warp - A1; }
    else                { t = 2; n = warp - A3; }

    const int srcoff_tab[3] = { OFF_GENE, OFF_PAT, OFF_GRP };
    const __half* h_src = h16buf + srcoff_tab[t];
    const int* off = g_off[t];
    const int* col = g_col[t];

    const int qr = lane >> 3;
    const int q8 = lane & 7;

    int o0 = off[n], o1 = off[n + 1];
    float2 acc[4];
#pragma unroll
    for (int k = 0; k < 4; k++) acc[k] = make_float2(0.f, 0.f);

    for (int base = o0; base < o1; base += 32) {
        int idx = (base + lane < o1) ? col[base + lane] : 0;
        int m = min(32, o1 - base);
#pragma unroll 4
        for (int j = 0; j < m; j += 4) {
            int jj = j + qr;
            int s = __shfl_sync(FULL, idx, jj & 31);
            if (jj < m) {
                float4 raw = ((const float4*)(h_src + (size_t)s * HID))[q8];
                const __half2* hp = (const __half2*)&raw;
#pragma unroll
                for (int k = 0; k < 4; k++) {
                    float2 f = __half22float2(hp[k]);
                    acc[k].x += f.x;
                    acc[k].y += f.y;
                }
            }
        }
    }
#pragma unroll
    for (int k = 0; k < 4; k++) {
        acc[k].x += __shfl_xor_sync(FULL, acc[k].x, 8);
        acc[k].y += __shfl_xor_sync(FULL, acc[k].y, 8);
        acc[k].x += __shfl_xor_sync(FULL, acc[k].x, 16);
        acc[k].y += __shfl_xor_sync(FULL, acc[k].y, 16);
    }
    if (qr == 0) {
        float inv = 1.f / fmaxf((float)(o1 - o0), 1.f);
        float4 w0 = make_float4(acc[0].x * inv, acc[0].y * inv, acc[1].x * inv, acc[1].y * inv);
        float4 w1 = make_float4(acc[2].x * inv, acc[2].y * inv, acc[3].x * inv, acc[3].y * inv);
        float4* dstp = (float4*)&agg[(size_t)warp * HID + q8 * 8];
        dstp[0] = w0;
        dstp[1] = w1;
    }
}

// ---------------- fused SAGE linear + residual + LN + ELU ----------------
// grid = T0 [+ T1 if do_gene]. Patient tile: out = LN(h + A0@Wl0 + bl0 + R@Wr0),
// writes fp32 h. Gene mega-tile: sums e1+e3 branches (Wr folded), writes h16 only.
// dynamic smem: 6 x 4096 floats = 96 KB
__global__ void lin_fused_kernel(const float* __restrict__ agg,
                                 float* __restrict__ h,
                                 __half* __restrict__ h16,
                                 const float* __restrict__ convWl,  // layer base [4,64,64]
                                 const float* __restrict__ convbl,  // layer base [4,64]
                                 const float* __restrict__ convWr,
                                 const float* __restrict__ lnG,     // layer base [3,64]
                                 const float* __restrict__ lnB,
                                 int do_gene) {
    extern __shared__ float sm[];
    float* sWa = sm;            // Wl0 | Wl1
    float* sWb = sm + 4096;     // Wr0 | Wl3
    float* sWc = sm + 8192;     //  -  | Wr1+Wr3
    float* sTa = sm + 12288;    // A0  | A1
    float* sTb = sm + 16384;    // R   | A3
    float* sTc = sm + 20480;    //  -  | R

    int b = blockIdx.x;
    bool pat = (b < T0);
    int tile = pat ? b : b - T0;
    int N    = pat ? NP : NG;
    int lnT  = pat ? 1 : 0;   // LN param index within layer (gene=0, patient=1)

    int tx = threadIdx.x & 15;
    int ty = threadIdx.x >> 4;
    int j0 = tx * 4;
    int nb = ty * 4;

    float4 bias;
    if (pat) {
        const float* Wl = convWl;            // e0
        const float* Wr = convWr;
        for (int i = threadIdx.x; i < 4096; i += 256) {
            sWa[i] = Wl[i];
            sWb[i] = Wr[i];
        }
        bias = *(const float4*)(convbl + j0);
    } else {
        const float* Wl1 = convWl + (size_t)1 * HID * HID;
        const float* Wl3 = convWl + (size_t)3 * HID * HID;
        const float* Wr1 = convWr + (size_t)1 * HID * HID;
        const float* Wr3 = convWr + (size_t)3 * HID * HID;
        for (int i = threadIdx.x; i < 4096; i += 256) {
            sWa[i] = Wl1[i];
            sWb[i] = Wl3[i];
            sWc[i] = Wr1[i] + Wr3[i];
        }
        float4 b1 = *(const float4*)(convbl + HID + j0);
        float4 b3 = *(const float4*)(convbl + 3 * HID + j0);
        bias = make_float4(b1.x + b3.x, b1.y + b3.y, b1.z + b3.z, b1.w + b3.w);
    }

    int n0 = tile * 64;
    // stage input tiles
    if (pat) {
        const float* h_root = h + OFF_PAT;
        for (int i = threadIdx.x; i < 64 * 16; i += 256) {
            int nn = i >> 4, q = i & 15;
            int n = n0 + nn;
            float4 va = make_float4(0.f, 0.f, 0.f, 0.f), vr = va;
            if (n < N) {
                va = ((const float4*)(agg + (size_t)(A0 + n) * HID))[q];
                vr = ((const float4*)(h_root + (size_t)n * HID))[q];
            }
            *(float4*)&sTa[nn * 64 + q * 4] = va;
            *(float4*)&sTb[nn * 64 + q * 4] = vr;
        }
    } else {
        const float* h_root = h + OFF_GENE;
        for (int i = threadIdx.x; i < 64 * 16; i += 256) {
            int nn = i >> 4, q = i & 15;
            int n = n0 + nn;
            float4 v1 = make_float4(0.f, 0.f, 0.f, 0.f), v3 = v1, vr = v1;
            if (n < N) {
                v1 = ((const float4*)(agg + (size_t)(A1 + n) * HID))[q];
                v3 = ((const float4*)(agg + (size_t)(A3 + n) * HID))[q];
                vr = ((const float4*)(h_root + (size_t)n * HID))[q];
            }
            *(float4*)&sTa[nn * 64 + q * 4] = v1;
            *(float4*)&sTb[nn * 64 + q * 4] = v3;
            *(float4*)&sTc[nn * 64 + q * 4] = vr;
        }
    }
    __syncthreads();

    float acc[4][4];
#pragma unroll
    for (int i = 0; i < 4; i++) {
        acc[i][0] = bias.x; acc[i][1] = bias.y; acc[i][2] = bias.z; acc[i][3] = bias.w;
    }
    if (pat) {
#pragma unroll 8
        for (int k = 0; k < 64; k++) {
            float4 wa = *(const float4*)&sWa[k * 64 + j0];
            float4 wb = *(const float4*)&sWb[k * 64 + j0];
#pragma unroll
            for (int i = 0; i < 4; i++) {
                float a = sTa[(nb + i) * 64 + k];
                float r = sTb[(nb + i) * 64 + k];
                acc[i][0] += a * wa.x + r * wb.x;
                acc[i][1] += a * wa.y + r * wb.y;
                acc[i][2] += a * wa.z + r * wb.z;
                acc[i][3] += a * wa.w + r * wb.w;
            }
        }
    } else {
#pragma unroll 4
        for (int k = 0; k < 64; k++) {
            float4 wa = *(const float4*)&sWa[k * 64 + j0];
            float4 wb = *(const float4*)&sWb[k * 64 + j0];
            float4 wc = *(const float4*)&sWc[k * 64 + j0];
#pragma unroll
            for (int i = 0; i < 4; i++) {
                float a1 = sTa[(nb + i) * 64 + k];
                float a3 = sTb[(nb + i) * 64 + k];
                float r  = sTc[(nb + i) * 64 + k];
                acc[i][0] += a1 * wa.x + a3 * wb.x + r * wc.x;
                acc[i][1] += a1 * wa.y + a3 * wb.y + r * wc.y;
                acc[i][2] += a1 * wa.z + a3 * wb.z + r * wc.z;
                acc[i][3] += a1 * wa.w + a3 * wb.w + r * wc.w;
            }
        }
    }

    // residual + LN + ELU per row; row nb+i is held by the 16 threads of this ty group
    const float* gamma = lnG + lnT * HID;
    const float* beta  = lnB + lnT * HID;
    float4 gm = *(const float4*)(gamma + j0);
    float4 bt = *(const float4*)(beta + j0);
    size_t hoff = pat ? (size_t)OFF_PAT : (size_t)OFF_GENE;

#pragma unroll
    for (int i = 0; i < 4; i++) {
        int n = n0 + nb + i;
        // residual add (h master row)
        float4 hv = make_float4(0.f, 0.f, 0.f, 0.f);
        if (n < N) hv = *(const float4*)(h + hoff + (size_t)n * HID + j0);
        float e0 = acc[i][0] + hv.x;
        float e1 = acc[i][1] + hv.y;
        float e2 = acc[i][2] + hv.z;
        float e3 = acc[i][3] + hv.w;
        float s = e0 + e1 + e2 + e3;
#pragma unroll
        for (int o = 1; o < 16; o <<= 1) s += __shfl_xor_sync(FULL, s, o);
        float mean = s * (1.f / 64.f);
        float d0 = e0 - mean, d1 = e1 - mean, d2 = e2 - mean, d3 = e3 - mean;
        float v = d0 * d0 + d1 * d1 + d2 * d2 + d3 * d3;
#pragma unroll
        for (int o = 1; o < 16; o <<= 1) v += __shfl_xor_sync(FULL, v, o);
        float rstd = rsqrtf(v * (1.f / 64.f) + 1e-5f);
        float y0 = elu1(d0 * rstd * gm.x + bt.x);
        float y1 = elu1(d1 * rstd * gm.y + bt.y);
        float y2 = elu1(d2 * rstd * gm.z + bt.z);
        float y3 = elu1(d3 * rstd * gm.w + bt.w);
        if (n < N) {
            if (pat) {
                *(float4*)(h + hoff + (size_t)n * HID + j0) =
                    make_float4(y0, y1, y2, y3);
            } else {
                __half2* hp = (__half2*)(h16 + (size_t)n * HID + j0);
                hp[0] = __floats2half2_rn(y0, y1);
                hp[1] = __floats2half2_rn(y2, y3);
            }
        }
    }
}

// ---------------- cox head: one warp per patient ----------------
__global__ void cox_kernel(const float* __restrict__ h,
                           const float* __restrict__ W1,
                           const float* __restrict__ b1,
                           const float* __restrict__ W2,
                           const float* __restrict__ b2,
                           float* __restrict__ out, int N) {
    __shared__ float sW1[HID * 32];
    __shared__ float sb1[32];
    __shared__ float sW2[32];
    __shared__ float sb2;
    for (int i = threadIdx.x; i < HID * 32; i += blockDim.x) sW1[i] = W1[i];
    if (threadIdx.x < 32) { sb1[threadIdx.x] = b1[threadIdx.x]; sW2[threadIdx.x] = W2[threadIdx.x]; }
    if (threadIdx.x == 0) sb2 = b2[0];
    __syncthreads();

    int warp = (blockIdx.x * blockDim.x + threadIdx.x) >> 5;
    int lane = threadIdx.x & 31;
    if (warp >= N) return;
    size_t base = (size_t)warp * HID;
    float a = h[base + lane];
    float c = h[base + 32 + lane];
    float z = sb1[lane];
#pragma unroll
    for (int k = 0; k < 32; k++) {
        float hk = __shfl_sync(FULL, a, k);
        z += hk * sW1[k * 32 + lane];
    }
#pragma unroll
    for (int k = 0; k < 32; k++) {
        float hk = __shfl_sync(FULL, c, k);
        z += hk * sW1[(k + 32) * 32 + lane];
    }
    z = elu1(z);
    float hz = z * sW2[lane];
#pragma unroll
    for (int o = 16; o; o >>= 1) hz += __shfl_xor_sync(FULL, hz, o);
    if (lane == 0) out[warp] = hz + sb2;
}

// ---------------- host launcher ----------------
static inline int cdiv(long long a, long long b) { return (int)((a + b - 1) / b); }

extern "C" void kernel_launch(void* const* d_in, const int* in_sizes, int n_in,
                              void* d_out, int out_size) {
    const float* x_gene = (const float*)d_in[0];
    const float* x_pat  = (const float*)d_in[1];
    const float* x_grp  = (const float*)d_in[2];
    const int* src0 = (const int*)d_in[3];
    const int* dst0 = (const int*)d_in[4];
    const int* src1 = (const int*)d_in[5];
    const int* dst1 = (const int*)d_in[6];
    // d_in[7], d_in[8]: src2/dst2 (gene->mutation_group) — dead for the output
    const int* src3 = (const int*)d_in[9];
    const int* dst3 = (const int*)d_in[10];
    const float* encGW = (const float*)d_in[11];
    const float* encGb = (const float*)d_in[12];
    const float* encPW = (const float*)d_in[13];
    const float* encPb = (const float*)d_in[14];
    const float* encMW = (const float*)d_in[15];
    const float* encMb = (const float*)d_in[16];
    const float* convWl = (const float*)d_in[17];   // [2,4,64,64]
    const float* convbl = (const float*)d_in[18];   // [2,4,64]
    const float* convWr = (const float*)d_in[19];   // [2,4,64,64]
    const float* lnG = (const float*)d_in[20];      // [2,3,64]
    const float* lnB = (const float*)d_in[21];
    const float* coxW1 = (const float*)d_in[22];
    const float* coxb1 = (const float*)d_in[23];
    const float* coxW2 = (const float*)d_in[24];
    const float* coxb2 = (const float*)d_in[25];
    float* out = (float*)d_out;

    const int E = in_sizes[3];

    float *hbuf, *aggbuf;
    __half* h16buf;
    cudaGetSymbolAddress((void**)&hbuf,   g_h);
    cudaGetSymbolAddress((void**)&h16buf, g_h16);
    cudaGetSymbolAddress((void**)&aggbuf, g_agg);

    float* h_pat = hbuf + OFF_PAT;

    static const int LIN_SMEM = 6 * 4096 * (int)sizeof(float);   // 96 KB
    cudaFuncSetAttribute(lin_fused_kernel,
                         cudaFuncAttributeMaxDynamicSharedMemorySize, LIN_SMEM);

    // [1] merged encoders
    enc_all_kernel<<<cdiv((long long)NTOT * HID, 256), 256>>>(
        x_gene, x_pat, x_grp, encGW, encGb, encPW, encPb, encMW, encMb,
        hbuf, h16buf);

    // [2-5] CSR build for live types {e0, e1, e3} (g_cnt zero by invariant)
    count_all_kernel<<<cdiv(3LL * E, 256), 256>>>(dst0, dst1, dst3, E);
    scanA_kernel<<<NBTOT, 256>>>();
    scanC_kernel<<<NBTOT, 256>>>(E);
    fill_all_kernel<<<cdiv(3LL * E, 256), 256>>>(src0, dst0, src1, dst1, src3, dst3, E);

    // [6-7] layer 1: pull e0,e1,e3 then fused linear+LN (patient fp32, gene fp16)
    pull_all_kernel<<<cdiv((long long)NSEG1 * 32, 256), 256>>>(h16buf, aggbuf, NSEG1);
    lin_fused_kernel<<<T0 + T1, 256, LIN_SMEM>>>(
        aggbuf, hbuf, h16buf, convWl, convbl, convWr, lnG, lnB, 1);

    // [8-9] layer 2: pull e0 only, fused linear+LN (patient fp32)
    pull_all_kernel<<<cdiv((long long)NP * 32, 256), 256>>>(h16buf, aggbuf, NP);
    lin_fused_kernel<<<T0, 256, LIN_SMEM>>>(
        aggbuf, hbuf, h16buf,
        convWl + (size_t)4 * HID * HID,
        convbl + (size_t)4 * HID,
        convWr + (size_t)4 * HID * HID,
        lnG + (size_t)3 * HID,
        lnB + (size_t)3 * HID, 0);

    // [10] cox head
    cox_kernel<<<cdiv((long long)NP * 32, 256), 256>>>(h_pat, coxW1, coxb1, coxW2, coxb2, out, NP);
}

// round 14
// speedup vs baseline: 1.0333x; 1.0333x over previous
#include <cuda_runtime.h>
#include <cuda_bf16.h>
#include <cuda_fp16.h>
#include <math.h>

#define NG 20000
#define NP 100000
#define NM 5000
#define NTOT (NG + NP + NM)
#define HID 64
#define EMAX 1000000
#define FULL 0xFFFFFFFFu

// live edge types (orig ids): 0: gene->patient, 1: patient->gene, 2(orig 3): group->gene
// segment layout for agg: e0 | e1 | e3
#define A0 0
#define A1 NP
#define A3 (NP + NG)
#define NSEG1 (NP + 2 * NG)          // layer-1 pull covers all three
// tiles
#define T0 ((NP + 63) / 64)          // patient tiles
#define T1 ((NG + 63) / 64)          // gene mega-tiles
// scan chunking
#define SCH 1024
#define NB0 ((NP + SCH - 1) / SCH)   // 98
#define NB1 ((NG + SCH - 1) / SCH)   // 20
#define NB3 NB1                      // 20
#define NBTOT (NB0 + NB1 + NB3)      // 138

// ---------------- scratch (static device globals; no allocs) ----------------
__device__ float  g_h  [NTOT * HID];               // fp32 master [gene|patient|group]
__device__ __align__(16) __half g_h16[NTOT * HID]; // fp16 gather mirror
__device__ float  g_agg[NSEG1 * HID];
__device__ int    g_cnt[3][NP];      // zero at load; scanC restores zeros each call
__device__ int    g_off[3][NP + 1];
__device__ int    g_cur[3][NP + 1];
__device__ int    g_col[3][EMAX];
__device__ int    g_part[NBTOT];

#define OFF_GENE 0
#define OFF_PAT  (NG * HID)
#define OFF_GRP  ((NG + NP) * HID)

__device__ __forceinline__ float elu1(float x) { return x > 0.f ? x : expm1f(x); }

__constant__ int c_Ns[3] = { NP, NG, NG };

__device__ __forceinline__ void decode_scan_block(int b, int& t, int& c) {
    if      (b < NB0)       { t = 0; c = b; }
    else if (b < NB0 + NB1) { t = 1; c = b - NB0; }
    else                    { t = 2; c = b - NB0 - NB1; }
}

// ---------------- merged encoder ----------------
__global__ void enc_all_kernel(const float* __restrict__ x_gene,
                               const float* __restrict__ x_pat,
                               const float* __restrict__ x_grp,
                               const float* __restrict__ Wg, const float* __restrict__ bg,
                               const float* __restrict__ Wp, const float* __restrict__ bp,
                               const float* __restrict__ Wm, const float* __restrict__ bm,
                               float* __restrict__ h, __half* __restrict__ h16) {
    int idx = blockIdx.x * blockDim.x + threadIdx.x;
    if (idx >= NTOT * HID) return;
    int n = idx >> 6;
    int j = idx & 63;
    const float* x; const float* W; const float* b; int K; int row; bool wf32;
    if (n < NG)           { x = x_gene; W = Wg; b = bg; K = 11; row = n;            wf32 = true; }
    else if (n < NG + NP) { x = x_pat;  W = Wp; b = bp; K = 3;  row = n - NG;       wf32 = true; }
    else                  { x = x_grp;  W = Wm; b = bm; K = 4;  row = n - NG - NP;  wf32 = false; }
    float acc = b[j];
    for (int k = 0; k < K; k++)
        acc += x[row * K + k] * W[k * HID + j];
    float y = elu1(acc);
    if (wf32) h[idx] = y;
    h16[idx] = __float2half(y);
}

// ---------------- CSR build ----------------
__global__ void count_all_kernel(const int* __restrict__ d0, const int* __restrict__ d1,
                                 const int* __restrict__ d3, int E) {
    int i = blockIdx.x * blockDim.x + threadIdx.x;
    if (i >= 3 * E) return;
    int t = (i >= E) + (i >= 2 * E);
    int j = i - t * E;
    const int* d = (t == 0) ? d0 : (t == 1) ? d1 : d3;
    atomicAdd(&g_cnt[t][d[j]], 1);
}

__global__ void scanA_kernel() {
    int t, c;
    decode_scan_block(blockIdx.x, t, c);
    int N = c_Ns[t];
    const int* cnt = g_cnt[t];
    int base = c * SCH + threadIdx.x * 4;
    int s = 0;
#pragma unroll
    for (int k = 0; k < 4; k++) {
        int i = base + k;
        if (i < N) s += cnt[i];
    }
    __shared__ int wsum[8];
    int lane = threadIdx.x & 31, wid = threadIdx.x >> 5;
#pragma unroll
    for (int o = 16; o; o >>= 1) s += __shfl_xor_sync(FULL, s, o);
    if (lane == 0) wsum[wid] = s;
    __syncthreads();
    if (threadIdx.x == 0) {
        int tot = 0;
#pragma unroll
        for (int w = 0; w < 8; w++) tot += wsum[w];
        g_part[blockIdx.x] = tot;
    }
}

__global__ void scanC_kernel(int E) {
    int t, c;
    decode_scan_block(blockIdx.x, t, c);
    int N = c_Ns[t];
    int* cnt = g_cnt[t];
    int* off = g_off[t];
    int* cur = g_cur[t];

    __shared__ int s_carry;
    int lane = threadIdx.x & 31, wid = threadIdx.x >> 5;
    if (wid == 0) {
        int pb = (t == 0) ? 0 : (t == 1) ? NB0 : NB0 + NB1;
        int sum = 0;
        for (int i = lane; i < c; i += 32) sum += g_part[pb + i];
#pragma unroll
        for (int o = 16; o; o >>= 1) sum += __shfl_xor_sync(FULL, sum, o);
        if (lane == 0) s_carry = sum;
    }
    __syncthreads();
    int carry = s_carry;

    int base = c * SCH + threadIdx.x * 4;
    int v[4];
    int tsum = 0;
#pragma unroll
    for (int k = 0; k < 4; k++) {
        int i = base + k;
        v[k] = (i < N) ? cnt[i] : 0;
        tsum += v[k];
    }
    __shared__ int wsum[8];
    int x = tsum;
#pragma unroll
    for (int o = 1; o < 32; o <<= 1) { int tt = __shfl_up_sync(FULL, x, o); if (lane >= o) x += tt; }
    if (lane == 31) wsum[wid] = x;
    __syncthreads();
    if (wid == 0 && lane < 8) {
        int w = wsum[lane];
#pragma unroll
        for (int o = 1; o < 8; o <<= 1) { int tt = __shfl_up_sync(0xFFu, w, o); if (lane >= o) w += tt; }
        wsum[lane] = w;
    }
    __syncthreads();
    int excl = (x - tsum) + (wid > 0 ? wsum[wid - 1] : 0) + carry;
#pragma unroll
    for (int k = 0; k < 4; k++) {
        int i = base + k;
        if (i < N) { off[i] = excl; cur[i] = excl; cnt[i] = 0; }
        excl += v[k];
    }
    if (threadIdx.x == 0 && c == (N + SCH - 1) / SCH - 1) off[N] = E;
}

__global__ void fill_all_kernel(const int* __restrict__ s0, const int* __restrict__ d0,
                                const int* __restrict__ s1, const int* __restrict__ d1,
                                const int* __restrict__ s3, const int* __restrict__ d3,
                                int E) {
    int i = blockIdx.x * blockDim.x + threadIdx.x;
    if (i >= 3 * E) return;
    int t = (i >= E) + (i >= 2 * E);
    int j = i - t * E;
    const int* s = (t == 0) ? s0 : (t == 1) ? s1 : s3;
    const int* d = (t == 0) ? d0 : (t == 1) ? d1 : d3;
    int p = atomicAdd(&g_cur[t][d[j]], 1);
    g_col[t][p] = s[j];
}

// ---------------- pull aggregation (mean), fp16 gather ----------------
__global__ void pull_all_kernel(const __half* __restrict__ h16buf,
                                float* __restrict__ agg, int nseg) {
    int warp = (blockIdx.x * blockDim.x + threadIdx.x) >> 5;
    int lane = threadIdx.x & 31;
    if (warp >= nseg) return;

    int t, n;
    if      (warp < A1) { t = 0; n = warp; }
    else if (warp < A3) { t = 1; n = warp - A1; }
    else                { t = 2; n = warp - A3; }

    const int srcoff_tab[3] = { OFF_GENE, OFF_PAT, OFF_GRP };
    const __half* h_src = h16buf + srcoff_tab[t];
    const int* off = g_off[t];
    const int* col = g_col[t];

    const int qr = lane >> 3;
    const int q8 = lane & 7;

    int o0 = off[n], o1 = off[n + 1];
    float2 acc[4];
#pragma unroll
    for (int k = 0; k < 4; k++) acc[k] = make_float2(0.f, 0.f);

    for (int base = o0; base < o1; base += 32) {
        int idx = (base + lane < o1) ? col[base + lane] : 0;
        int m = min(32, o1 - base);
#pragma unroll 4
        for (int j = 0; j < m; j += 4) {
            int jj = j + qr;
            int s = __shfl_sync(FULL, idx, jj & 31);
            if (jj < m) {
                float4 raw = ((const float4*)(h_src + (size_t)s * HID))[q8];
                const __half2* hp = (const __half2*)&raw;
#pragma unroll
                for (int k = 0; k < 4; k++) {
                    float2 f = __half22float2(hp[k]);
                    acc[k].x += f.x;
                    acc[k].y += f.y;
                }
            }
        }
    }
#pragma unroll
    for (int k = 0; k < 4; k++) {
        acc[k].x += __shfl_xor_sync(FULL, acc[k].x, 8);
        acc[k].y += __shfl_xor_sync(FULL, acc[k].y, 8);
        acc[k].x += __shfl_xor_sync(FULL, acc[k].x, 16);
        acc[k].y += __shfl_xor_sync(FULL, acc[k].y, 16);
    }
    if (qr == 0) {
        float inv = 1.f / fmaxf((float)(o1 - o0), 1.f);
        float4 w0 = make_float4(acc[0].x * inv, acc[0].y * inv, acc[1].x * inv, acc[1].y * inv);
        float4 w1 = make_float4(acc[2].x * inv, acc[2].y * inv, acc[3].x * inv, acc[3].y * inv);
        float4* dstp = (float4*)&agg[(size_t)warp * HID + q8 * 8];
        dstp[0] = w0;
        dstp[1] = w1;
    }
}

// ---------------- patient fused linear + residual + LN + ELU (64 KB smem) ----------------
// out_pat = LN(h_pat + A0@Wl + bl + h_pat@Wr); writes fp32 h.
__global__ void lin_pat_kernel(const float* __restrict__ agg,
                               float* __restrict__ h,
                               const float* __restrict__ Wl,
                               const float* __restrict__ bl,
                               const float* __restrict__ Wr,
                               const float* __restrict__ gamma,
                               const float* __restrict__ beta) {
    extern __shared__ float sm[];
    float* sWl = sm;
    float* sWr = sm + 4096;
    float* sA  = sm + 8192;
    float* sR  = sm + 12288;

    for (int i = threadIdx.x; i < 4096; i += 256) {
        sWl[i] = Wl[i];
        sWr[i] = Wr[i];
    }
    int tx = threadIdx.x & 15;
    int ty = threadIdx.x >> 4;
    int j0 = tx * 4;
    int nb = ty * 4;
    float4 bias = *(const float4*)(bl + j0);

    int n0 = blockIdx.x * 64;
    const float* h_root = h + OFF_PAT;
    for (int i = threadIdx.x; i < 64 * 16; i += 256) {
        int nn = i >> 4, q = i & 15;
        int n = n0 + nn;
        float4 va = make_float4(0.f, 0.f, 0.f, 0.f), vr = va;
        if (n < NP) {
            va = ((const float4*)(agg + (size_t)(A0 + n) * HID))[q];
            vr = ((const float4*)(h_root + (size_t)n * HID))[q];
        }
        *(float4*)&sA[nn * 64 + q * 4] = va;
        *(float4*)&sR[nn * 64 + q * 4] = vr;
    }
    __syncthreads();

    float acc[4][4];
#pragma unroll
    for (int i = 0; i < 4; i++) {
        acc[i][0] = bias.x; acc[i][1] = bias.y; acc[i][2] = bias.z; acc[i][3] = bias.w;
    }
#pragma unroll 8
    for (int k = 0; k < 64; k++) {
        float4 wa = *(const float4*)&sWl[k * 64 + j0];
        float4 wb = *(const float4*)&sWr[k * 64 + j0];
#pragma unroll
        for (int i = 0; i < 4; i++) {
            float a = sA[(nb + i) * 64 + k];
            float r = sR[(nb + i) * 64 + k];
            acc[i][0] += a * wa.x + r * wb.x;
            acc[i][1] += a * wa.y + r * wb.y;
            acc[i][2] += a * wa.z + r * wb.z;
            acc[i][3] += a * wa.w + r * wb.w;
        }
    }

    float4 gm = *(const float4*)(gamma + j0);
    float4 bt = *(const float4*)(beta + j0);
#pragma unroll
    for (int i = 0; i < 4; i++) {
        int n = n0 + nb + i;
        float4 hv = make_float4(0.f, 0.f, 0.f, 0.f);
        if (n < NP) hv = *(const float4*)(h + OFF_PAT + (size_t)n * HID + j0);
        float e0 = acc[i][0] + hv.x;
        float e1 = acc[i][1] + hv.y;
        float e2 = acc[i][2] + hv.z;
        float e3 = acc[i][3] + hv.w;
        float s = e0 + e1 + e2 + e3;
#pragma unroll
        for (int o = 1; o < 16; o <<= 1) s += __shfl_xor_sync(FULL, s, o);
        float mean = s * (1.f / 64.f);
        float d0 = e0 - mean, d1 = e1 - mean, d2 = e2 - mean, d3 = e3 - mean;
        float v = d0 * d0 + d1 * d1 + d2 * d2 + d3 * d3;
#pragma unroll
        for (int o = 1; o < 16; o <<= 1) v += __shfl_xor_sync(FULL, v, o);
        float rstd = rsqrtf(v * (1.f / 64.f) + 1e-5f);
        if (n < NP) {
            *(float4*)(h + OFF_PAT + (size_t)n * HID + j0) = make_float4(
                elu1(d0 * rstd * gm.x + bt.x),
                elu1(d1 * rstd * gm.y + bt.y),
                elu1(d2 * rstd * gm.z + bt.z),
                elu1(d3 * rstd * gm.w + bt.w));
        }
    }
}

// ---------------- gene fused mega-tile (96 KB smem) ----------------
// out_gene = LN(h_gene + A1@Wl1 + A3@Wl3 + (bl1+bl3) + h_gene@(Wr1+Wr3)); writes fp16 only.
__global__ void lin_gene_kernel(const float* __restrict__ agg,
                                const float* __restrict__ h,
                                __half* __restrict__ h16,
                                const float* __restrict__ convWl,  // layer base
                                const float* __restrict__ convbl,
                                const float* __restrict__ convWr,
                                const float* __restrict__ gamma,   // gene LN params
                                const float* __restrict__ beta) {
    extern __shared__ float sm[];
    float* sWa = sm;            // Wl1
    float* sWb = sm + 4096;     // Wl3
    float* sWc = sm + 8192;     // Wr1+Wr3
    float* sTa = sm + 12288;    // A1
    float* sTb = sm + 16384;    // A3
    float* sTc = sm + 20480;    // R

    const float* Wl1 = convWl + (size_t)1 * HID * HID;
    const float* Wl3 = convWl + (size_t)3 * HID * HID;
    const float* Wr1 = convWr + (size_t)1 * HID * HID;
    const float* Wr3 = convWr + (size_t)3 * HID * HID;
    for (int i = threadIdx.x; i < 4096; i += 256) {
        sWa[i] = Wl1[i];
        sWb[i] = Wl3[i];
        sWc[i] = Wr1[i] + Wr3[i];
    }
    int tx = threadIdx.x & 15;
    int ty = threadIdx.x >> 4;
    int j0 = tx * 4;
    int nb = ty * 4;
    float4 b1 = *(const float4*)(convbl + HID + j0);
    float4 b3 = *(const float4*)(convbl + 3 * HID + j0);
    float4 bias = make_float4(b1.x + b3.x, b1.y + b3.y, b1.z + b3.z, b1.w + b3.w);

    int n0 = blockIdx.x * 64;
    for (int i = threadIdx.x; i < 64 * 16; i += 256) {
        int nn = i >> 4, q = i & 15;
        int n = n0 + nn;
        float4 v1 = make_float4(0.f, 0.f, 0.f, 0.f), v3 = v1, vr = v1;
        if (n < NG) {
            v1 = ((const float4*)(agg + (size_t)(A1 + n) * HID))[q];
            v3 = ((const float4*)(agg + (size_t)(A3 + n) * HID))[q];
            vr = ((const float4*)(h + (size_t)n * HID))[q];
        }
        *(float4*)&sTa[nn * 64 + q * 4] = v1;
        *(float4*)&sTb[nn * 64 + q * 4] = v3;
        *(float4*)&sTc[nn * 64 + q * 4] = vr;
    }
    __syncthreads();

    float acc[4][4];
#pragma unroll
    for (int i = 0; i < 4; i++) {
        acc[i][0] = bias.x; acc[i][1] = bias.y; acc[i][2] = bias.z; acc[i][3] = bias.w;
    }
#pragma unroll 4
    for (int k = 0; k < 64; k++) {
        float4 wa = *(const float4*)&sWa[k * 64 + j0];
        float4 wb = *(const float4*)&sWb[k * 64 + j0];
        float4 wc = *(const float4*)&sWc[k * 64 + j0];
#pragma unroll
        for (int i = 0; i < 4; i++) {
            float a1 = sTa[(nb + i) * 64 + k];
            float a3 = sTb[(nb + i) * 64 + k];
            float r  = sTc[(nb + i) * 64 + k];
            acc[i][0] += a1 * wa.x + a3 * wb.x + r * wc.x;
            acc[i][1] += a1 * wa.y + a3 * wb.y + r * wc.y;
            acc[i][2] += a1 * wa.z + a3 * wb.z + r * wc.z;
            acc[i][3] += a1 * wa.w + a3 * wb.w + r * wc.w;
        }
    }

    float4 gm = *(const float4*)(gamma + j0);
    float4 bt = *(const float4*)(beta + j0);
#pragma unroll
    for (int i = 0; i < 4; i++) {
        int n = n0 + nb + i;
        // residual: gene row already staged in sTc
        float e0 = acc[i][0] + sTc[(nb + i) * 64 + j0];
        float e1 = acc[i][1] + sTc[(nb + i) * 64 + j0 + 1];
        float e2 = acc[i][2] + sTc[(nb + i) * 64 + j0 + 2];
        float e3 = acc[i][3] + sTc[(nb + i) * 64 + j0 + 3];
        float s = e0 + e1 + e2 + e3;
#pragma unroll
        for (int o = 1; o < 16; o <<= 1) s += __shfl_xor_sync(FULL, s, o);
        float mean = s * (1.f / 64.f);
        float d0 = e0 - mean, d1 = e1 - mean, d2 = e2 - mean, d3 = e3 - mean;
        float v = d0 * d0 + d1 * d1 + d2 * d2 + d3 * d3;
#pragma unroll
        for (int o = 1; o < 16; o <<= 1) v += __shfl_xor_sync(FULL, v, o);
        float rstd = rsqrtf(v * (1.f / 64.f) + 1e-5f);
        if (n < NG) {
            __half2* hp = (__half2*)(h16 + (size_t)n * HID + j0);
            hp[0] = __floats2half2_rn(elu1(d0 * rstd * gm.x + bt.x),
                                      elu1(d1 * rstd * gm.y + bt.y));
            hp[1] = __floats2half2_rn(elu1(d2 * rstd * gm.z + bt.z),
                                      elu1(d3 * rstd * gm.w + bt.w));
        }
    }
}

// ---------------- cox head: one warp per patient ----------------
__global__ void cox_kernel(const float* __restrict__ h,
                           const float* __restrict__ W1,
                           const float* __restrict__ b1,
                           const float* __restrict__ W2,
                           const float* __restrict__ b2,
                           float* __restrict__ out, int N) {
    __shared__ float sW1[HID * 32];
    __shared__ float sb1[32];
    __shared__ float sW2[32];
    __shared__ float sb2;
    for (int i = threadIdx.x; i < HID * 32; i += blockDim.x) sW1[i] = W1[i];
    if (threadIdx.x < 32) { sb1[threadIdx.x] = b1[threadIdx.x]; sW2[threadIdx.x] = W2[threadIdx.x]; }
    if (threadIdx.x == 0) sb2 = b2[0];
    __syncthreads();

    int warp = (blockIdx.x * blockDim.x + threadIdx.x) >> 5;
    int lane = threadIdx.x & 31;
    if (warp >= N) return;
    size_t base = (size_t)warp * HID;
    float a = h[base + lane];
    float c = h[base + 32 + lane];
    float z = sb1[lane];
#pragma unroll
    for (int k = 0; k < 32; k++) {
        float hk = __shfl_sync(FULL, a, k);
        z += hk * sW1[k * 32 + lane];
    }
#pragma unroll
    for (int k = 0; k < 32; k++) {
        float hk = __shfl_sync(FULL, c, k);
        z += hk * sW1[(k + 32) * 32 + lane];
    }
    z = elu1(z);
    float hz = z * sW2[lane];
#pragma unroll
    for (int o = 16; o; o >>= 1) hz += __shfl_xor_sync(FULL, hz, o);
    if (lane == 0) out[warp] = hz + sb2;
}

// ---------------- host launcher ----------------
static inline int cdiv(long long a, long long b) { return (int)((a + b - 1) / b); }

extern "C" void kernel_launch(void* const* d_in, const int* in_sizes, int n_in,
                              void* d_out, int out_size) {
    const float* x_gene = (const float*)d_in[0];
    const float* x_pat  = (const float*)d_in[1];
    const float* x_grp  = (const float*)d_in[2];
    const int* src0 = (const int*)d_in[3];
    const int* dst0 = (const int*)d_in[4];
    const int* src1 = (const int*)d_in[5];
    const int* dst1 = (const int*)d_in[6];
    // d_in[7], d_in[8]: src2/dst2 — dead for the output
    const int* src3 = (const int*)d_in[9];
    const int* dst3 = (const int*)d_in[10];
    const float* encGW = (const float*)d_in[11];
    const float* encGb = (const float*)d_in[12];
    const float* encPW = (const float*)d_in[13];
    const float* encPb = (const float*)d_in[14];
    const float* encMW = (const float*)d_in[15];
    const float* encMb = (const float*)d_in[16];
    const float* convWl = (const float*)d_in[17];   // [2,4,64,64]
    const float* convbl = (const float*)d_in[18];   // [2,4,64]
    const float* convWr = (const float*)d_in[19];   // [2,4,64,64]
    const float* lnG = (const float*)d_in[20];      // [2,3,64]
    const float* lnB = (const float*)d_in[21];
    const float* coxW1 = (const float*)d_in[22];
    const float* coxb1 = (const float*)d_in[23];
    const float* coxW2 = (const float*)d_in[24];
    const float* coxb2 = (const float*)d_in[25];
    float* out = (float*)d_out;

    const int E = in_sizes[3];

    float *hbuf, *aggbuf;
    __half* h16buf;
    cudaGetSymbolAddress((void**)&hbuf,   g_h);
    cudaGetSymbolAddress((void**)&h16buf, g_h16);
    cudaGetSymbolAddress((void**)&aggbuf, g_agg);

    float* h_pat = hbuf + OFF_PAT;

    static const int PAT_SMEM  = 4 * 4096 * (int)sizeof(float);   // 64 KB
    static const int GENE_SMEM = 6 * 4096 * (int)sizeof(float);   // 96 KB
    cudaFuncSetAttribute(lin_pat_kernel,
                         cudaFuncAttributeMaxDynamicSharedMemorySize, PAT_SMEM);
    cudaFuncSetAttribute(lin_gene_kernel,
                         cudaFuncAttributeMaxDynamicSharedMemorySize, GENE_SMEM);

    // [1] merged encoders
    enc_all_kernel<<<cdiv((long long)NTOT * HID, 256), 256>>>(
        x_gene, x_pat, x_grp, encGW, encGb, encPW, encPb, encMW, encMb,
        hbuf, h16buf);

    // [2-5] CSR build for live types {e0, e1, e3}
    count_all_kernel<<<cdiv(3LL * E, 256), 256>>>(dst0, dst1, dst3, E);
    scanA_kernel<<<NBTOT, 256>>>();
    scanC_kernel<<<NBTOT, 256>>>(E);
    fill_all_kernel<<<cdiv(3LL * E, 256), 256>>>(src0, dst0, src1, dst1, src3, dst3, E);

    // [6-8] layer 1: pull e0,e1,e3; gene mega-tile (h16); patient fused LN (fp32)
    pull_all_kernel<<<cdiv((long long)NSEG1 * 32, 256), 256>>>(h16buf, aggbuf, NSEG1);
    lin_gene_kernel<<<T1, 256, GENE_SMEM>>>(
        aggbuf, hbuf, h16buf, convWl, convbl, convWr, lnG, lnB);
    lin_pat_kernel<<<T0, 256, PAT_SMEM>>>(
        aggbuf, hbuf, convWl, convbl, convWr, lnG + HID, lnB + HID);

    // [9-10] layer 2: pull e0 only; patient fused LN
    pull_all_kernel<<<cdiv((long long)NP * 32, 256), 256>>>(h16buf, aggbuf, NP);
    lin_pat_kernel<<<T0, 256, PAT_SMEM>>>(
        aggbuf, hbuf,
        convWl + (size_t)4 * HID * HID,
        convbl + (size_t)4 * HID,
        convWr + (size_t)4 * HID * HID,
        lnG + (size_t)3 * HID + HID,
        lnB + (size_t)3 * HID + HID);

    // [11] cox head
    cox_kernel<<<cdiv((long long)NP * 32, 256), 256>>>(h_pat, coxW1, coxb1, coxW2, coxb2, out, NP);
}

// round 15
// speedup vs baseline: 1.0825x; 1.0477x over previous
#include <cuda_runtime.h>
#include <cuda_bf16.h>
#include <cuda_fp16.h>
#include <math.h>

#define NG 20000
#define NP 100000
#define NM 5000
#define NTOT (NG + NP + NM)
#define HID 64
#define EMAX 1000000
#define FULL 0xFFFFFFFFu

// live edge types (orig ids): 0: gene->patient, 1: patient->gene, 2(orig 3): group->gene
// segment layout for agg: e0 | e1 | e3
#define A0 0
#define A1 NP
#define A3 (NP + NG)
#define NSEG1 (NP + 2 * NG)
// tiles
#define T0 ((NP + 63) / 64)
#define T1 ((NG + 63) / 64)
// encoder blocks in the merged enc+count launch
#define ENCB ((NTOT * HID + 255) / 256)
// scan chunking
#define SCH 1024
#define NB0 ((NP + SCH - 1) / SCH)
#define NB1 ((NG + SCH - 1) / SCH)
#define NB3 NB1
#define NBTOT (NB0 + NB1 + NB3)

// ---------------- scratch (static device globals; no allocs) ----------------
__device__ float  g_h  [NTOT * HID];               // fp32 master [gene|patient|group]
__device__ __align__(16) __half g_h16[NTOT * HID]; // fp16 gather mirror
__device__ float  g_agg[NSEG1 * HID];
__device__ int    g_cnt[3][NP];      // zero at load; scanC restores zeros each call
__device__ int    g_off[3][NP + 1];
__device__ int    g_cur[3][NP + 1];
__device__ int    g_col[3][EMAX];
__device__ int    g_part[NBTOT];

#define OFF_GENE 0
#define OFF_PAT  (NG * HID)
#define OFF_GRP  ((NG + NP) * HID)

__device__ __forceinline__ float elu1(float x) { return x > 0.f ? x : expm1f(x); }

__constant__ int c_Ns[3] = { NP, NG, NG };

__device__ __forceinline__ void decode_scan_block(int b, int& t, int& c) {
    if      (b < NB0)       { t = 0; c = b; }
    else if (b < NB0 + NB1) { t = 1; c = b - NB0; }
    else                    { t = 2; c = b - NB0 - NB1; }
}

// ---------------- merged encoder + degree count (independent work) ----------------
__global__ void enc_count_kernel(const float* __restrict__ x_gene,
                                 const float* __restrict__ x_pat,
                                 const float* __restrict__ x_grp,
                                 const float* __restrict__ Wg, const float* __restrict__ bg,
                                 const float* __restrict__ Wp, const float* __restrict__ bp,
                                 const float* __restrict__ Wm, const float* __restrict__ bm,
                                 float* __restrict__ h, __half* __restrict__ h16,
                                 const int* __restrict__ d0, const int* __restrict__ d1,
                                 const int* __restrict__ d3, int E) {
    if (blockIdx.x < ENCB) {
        int idx = blockIdx.x * blockDim.x + threadIdx.x;
        if (idx >= NTOT * HID) return;
        int n = idx >> 6;
        int j = idx & 63;
        const float* x; const float* W; const float* b; int K; int row; bool wf32;
        if (n < NG)           { x = x_gene; W = Wg; b = bg; K = 11; row = n;           wf32 = true; }
        else if (n < NG + NP) { x = x_pat;  W = Wp; b = bp; K = 3;  row = n - NG;      wf32 = true; }
        else                  { x = x_grp;  W = Wm; b = bm; K = 4;  row = n - NG - NP; wf32 = false; }
        float acc = b[j];
        for (int k = 0; k < K; k++)
            acc += x[row * K + k] * W[k * HID + j];
        float y = elu1(acc);
        if (wf32) h[idx] = y;
        h16[idx] = __float2half(y);
    } else {
        int i = (blockIdx.x - ENCB) * blockDim.x + threadIdx.x;
        if (i >= 3 * E) return;
        int t = (i >= E) + (i >= 2 * E);
        int j = i - t * E;
        const int* d = (t == 0) ? d0 : (t == 1) ? d1 : d3;
        atomicAdd(&g_cnt[t][d[j]], 1);
    }
}

// ---------------- CSR scan ----------------
__global__ void scanA_kernel() {
    int t, c;
    decode_scan_block(blockIdx.x, t, c);
    int N = c_Ns[t];
    const int* cnt = g_cnt[t];
    int base = c * SCH + threadIdx.x * 4;
    int s = 0;
#pragma unroll
    for (int k = 0; k < 4; k++) {
        int i = base + k;
        if (i < N) s += cnt[i];
    }
    __shared__ int wsum[8];
    int lane = threadIdx.x & 31, wid = threadIdx.x >> 5;
#pragma unroll
    for (int o = 16; o; o >>= 1) s += __shfl_xor_sync(FULL, s, o);
    if (lane == 0) wsum[wid] = s;
    __syncthreads();
    if (threadIdx.x == 0) {
        int tot = 0;
#pragma unroll
        for (int w = 0; w < 8; w++) tot += wsum[w];
        g_part[blockIdx.x] = tot;
    }
}

__global__ void scanC_kernel(int E) {
    int t, c;
    decode_scan_block(blockIdx.x, t, c);
    int N = c_Ns[t];
    int* cnt = g_cnt[t];
    int* off = g_off[t];
    int* cur = g_cur[t];

    __shared__ int s_carry;
    int lane = threadIdx.x & 31, wid = threadIdx.x >> 5;
    if (wid == 0) {
        int pb = (t == 0) ? 0 : (t == 1) ? NB0 : NB0 + NB1;
        int sum = 0;
        for (int i = lane; i < c; i += 32) sum += g_part[pb + i];
#pragma unroll
        for (int o = 16; o; o >>= 1) sum += __shfl_xor_sync(FULL, sum, o);
        if (lane == 0) s_carry = sum;
    }
    __syncthreads();
    int carry = s_carry;

    int base = c * SCH + threadIdx.x * 4;
    int v[4];
    int tsum = 0;
#pragma unroll
    for (int k = 0; k < 4; k++) {
        int i = base + k;
        v[k] = (i < N) ? cnt[i] : 0;
        tsum += v[k];
    }
    __shared__ int wsum[8];
    int x = tsum;
#pragma unroll
    for (int o = 1; o < 32; o <<= 1) { int tt = __shfl_up_sync(FULL, x, o); if (lane >= o) x += tt; }
    if (lane == 31) wsum[wid] = x;
    __syncthreads();
    if (wid == 0 && lane < 8) {
        int w = wsum[lane];
#pragma unroll
        for (int o = 1; o < 8; o <<= 1) { int tt = __shfl_up_sync(0xFFu, w, o); if (lane >= o) w += tt; }
        wsum[lane] = w;
    }
    __syncthreads();
    int excl = (x - tsum) + (wid > 0 ? wsum[wid - 1] : 0) + carry;
#pragma unroll
    for (int k = 0; k < 4; k++) {
        int i = base + k;
        if (i < N) { off[i] = excl; cur[i] = excl; cnt[i] = 0; }
        excl += v[k];
    }
    if (threadIdx.x == 0 && c == (N + SCH - 1) / SCH - 1) off[N] = E;
}

__global__ void fill_all_kernel(const int* __restrict__ s0, const int* __restrict__ d0,
                                const int* __restrict__ s1, const int* __restrict__ d1,
                                const int* __restrict__ s3, const int* __restrict__ d3,
                                int E) {
    int i = blockIdx.x * blockDim.x + threadIdx.x;
    if (i >= 3 * E) return;
    int t = (i >= E) + (i >= 2 * E);
    int j = i - t * E;
    const int* s = (t == 0) ? s0 : (t == 1) ? s1 : s3;
    const int* d = (t == 0) ? d0 : (t == 1) ? d1 : d3;
    int p = atomicAdd(&g_cur[t][d[j]], 1);
    g_col[t][p] = s[j];
}

// ---------------- pull aggregation (mean), fp16 gather ----------------
__global__ void pull_all_kernel(const __half* __restrict__ h16buf,
                                float* __restrict__ agg, int nseg) {
    int warp = (blockIdx.x * blockDim.x + threadIdx.x) >> 5;
    int lane = threadIdx.x & 31;
    if (warp >= nseg) return;

    int t, n;
    if      (warp < A1) { t = 0; n = warp; }
    else if (warp < A3) { t = 1; n = warp - A1; }
    else                { t = 2; n = warp - A3; }

    const int srcoff_tab[3] = { OFF_GENE, OFF_PAT, OFF_GRP };
    const __half* h_src = h16buf + srcoff_tab[t];
    const int* off = g_off[t];
    const int* col = g_col[t];

    const int qr = lane >> 3;
    const int q8 = lane & 7;

    int o0 = off[n], o1 = off[n + 1];
    float2 acc[4];
#pragma unroll
    for (int k = 0; k < 4; k++) acc[k] = make_float2(0.f, 0.f);

    for (int base = o0; base < o1; base += 32) {
        int idx = (base + lane < o1) ? col[base + lane] : 0;
        int m = min(32, o1 - base);
#pragma unroll 4
        for (int j = 0; j < m; j += 4) {
            int jj = j + qr;
            int s = __shfl_sync(FULL, idx, jj & 31);
            if (jj < m) {
                float4 raw = ((const float4*)(h_src + (size_t)s * HID))[q8];
                const __half2* hp = (const __half2*)&raw;
#pragma unroll
                for (int k = 0; k < 4; k++) {
                    float2 f = __half22float2(hp[k]);
                    acc[k].x += f.x;
                    acc[k].y += f.y;
                }
            }
        }
    }
#pragma unroll
    for (int k = 0; k < 4; k++) {
        acc[k].x += __shfl_xor_sync(FULL, acc[k].x, 8);
        acc[k].y += __shfl_xor_sync(FULL, acc[k].y, 8);
        acc[k].x += __shfl_xor_sync(FULL, acc[k].x, 16);
        acc[k].y += __shfl_xor_sync(FULL, acc[k].y, 16);
    }
    if (qr == 0) {
        float inv = 1.f / fmaxf((float)(o1 - o0), 1.f);
        float4 w0 = make_float4(acc[0].x * inv, acc[0].y * inv, acc[1].x * inv, acc[1].y * inv);
        float4 w1 = make_float4(acc[2].x * inv, acc[2].y * inv, acc[3].x * inv, acc[3].y * inv);
        float4* dstp = (float4*)&agg[(size_t)warp * HID + q8 * 8];
        dstp[0] = w0;
        dstp[1] = w1;
    }
}

// ---------------- patient fused linear + residual + LN + ELU [+ cox] (64 KB smem) ----
// do_cox=0: writes fp32 h_pat.  do_cox=1: keeps result in smem and computes the
// cox head in-block (identical summation order to the standalone cox), writes out[].
__global__ void lin_pat_kernel(const float* __restrict__ agg,
                               float* __restrict__ h,
                               const float* __restrict__ Wl,
                               const float* __restrict__ bl,
                               const float* __restrict__ Wr,
                               const float* __restrict__ gamma,
                               const float* __restrict__ beta,
                               const float* __restrict__ cW1,
                               const float* __restrict__ cb1,
                               const float* __restrict__ cW2,
                               const float* __restrict__ cb2,
                               float* __restrict__ out,
                               int do_cox) {
    extern __shared__ float sm[];
    float* sWl = sm;            // weights; later coxW1 (64x32) when do_cox
    float* sWr = sm + 4096;     // weights; later cb1|cW2|cb2
    float* sA  = sm + 8192;     // agg tile; later y tile when do_cox
    float* sR  = sm + 12288;    // root tile (also residual source)

    for (int i = threadIdx.x; i < 4096; i += 256) {
        sWl[i] = Wl[i];
        sWr[i] = Wr[i];
    }
    int tx = threadIdx.x & 15;
    int ty = threadIdx.x >> 4;
    int j0 = tx * 4;
    int nb = ty * 4;
    float4 bias = *(const float4*)(bl + j0);

    int n0 = blockIdx.x * 64;
    const float* h_root = h + OFF_PAT;
    for (int i = threadIdx.x; i < 64 * 16; i += 256) {
        int nn = i >> 4, q = i & 15;
        int n = n0 + nn;
        float4 va = make_float4(0.f, 0.f, 0.f, 0.f), vr = va;
        if (n < NP) {
            va = ((const float4*)(agg + (size_t)(A0 + n) * HID))[q];
            vr = ((const float4*)(h_root + (size_t)n * HID))[q];
        }
        *(float4*)&sA[nn * 64 + q * 4] = va;
        *(float4*)&sR[nn * 64 + q * 4] = vr;
    }
    __syncthreads();

    float acc[4][4];
#pragma unroll
    for (int i = 0; i < 4; i++) {
        acc[i][0] = bias.x; acc[i][1] = bias.y; acc[i][2] = bias.z; acc[i][3] = bias.w;
    }
#pragma unroll 8
    for (int k = 0; k < 64; k++) {
        float4 wa = *(const float4*)&sWl[k * 64 + j0];
        float4 wb = *(const float4*)&sWr[k * 64 + j0];
#pragma unroll
        for (int i = 0; i < 4; i++) {
            float a = sA[(nb + i) * 64 + k];
            float r = sR[(nb + i) * 64 + k];
            acc[i][0] += a * wa.x + r * wb.x;
            acc[i][1] += a * wa.y + r * wb.y;
            acc[i][2] += a * wa.z + r * wb.z;
            acc[i][3] += a * wa.w + r * wb.w;
        }
    }

    float4 gm = *(const float4*)(gamma + j0);
    float4 bt = *(const float4*)(beta + j0);
#pragma unroll
    for (int i = 0; i < 4; i++) {
        int n = n0 + nb + i;
        // residual from sR (same values as global h row)
        float e0 = acc[i][0] + sR[(nb + i) * 64 + j0];
        float e1 = acc[i][1] + sR[(nb + i) * 64 + j0 + 1];
        float e2 = acc[i][2] + sR[(nb + i) * 64 + j0 + 2];
        float e3 = acc[i][3] + sR[(nb + i) * 64 + j0 + 3];
        float s = e0 + e1 + e2 + e3;
#pragma unroll
        for (int o = 1; o < 16; o <<= 1) s += __shfl_xor_sync(FULL, s, o);
        float mean = s * (1.f / 64.f);
        float d0 = e0 - mean, d1 = e1 - mean, d2 = e2 - mean, d3 = e3 - mean;
        float v = d0 * d0 + d1 * d1 + d2 * d2 + d3 * d3;
#pragma unroll
        for (int o = 1; o < 16; o <<= 1) v += __shfl_xor_sync(FULL, v, o);
        float rstd = rsqrtf(v * (1.f / 64.f) + 1e-5f);
        float y0 = elu1(d0 * rstd * gm.x + bt.x);
        float y1 = elu1(d1 * rstd * gm.y + bt.y);
        float y2 = elu1(d2 * rstd * gm.z + bt.z);
        float y3 = elu1(d3 * rstd * gm.w + bt.w);
        if (do_cox) {
            // stash in own sA rows (each ty group owns rows nb..nb+3; no hazard)
            *(float4*)&sA[(nb + i) * 64 + j0] = make_float4(y0, y1, y2, y3);
        } else if (n < NP) {
            *(float4*)(h + OFF_PAT + (size_t)n * HID + j0) =
                make_float4(y0, y1, y2, y3);
        }
    }

    if (!do_cox) return;

    // ---- in-block cox head ----
    __syncthreads();
    // overwrite weight regions: sWl <- coxW1 (64x32), sWr[0..31] <- b1,
    // sWr[32..63] <- W2, sWr[64] <- b2
    for (int i = threadIdx.x; i < HID * 32; i += 256) sWl[i] = cW1[i];
    if (threadIdx.x < 32) {
        sWr[threadIdx.x] = cb1[threadIdx.x];
        sWr[32 + threadIdx.x] = cW2[threadIdx.x];
    }
    if (threadIdx.x == 0) sWr[64] = cb2[0];
    __syncthreads();

    int wid = threadIdx.x >> 5;
    int lane = threadIdx.x & 31;
    for (int r = wid * 8; r < wid * 8 + 8; r++) {
        int n = n0 + r;
        if (n >= NP) continue;
        float z = sWr[lane];                     // b1
        const float* yrow = &sA[r * 64];
#pragma unroll 8
        for (int k = 0; k < 64; k++) {
            z += yrow[k] * sWl[k * 32 + lane];   // broadcast LDS + W1 col
        }
        z = elu1(z);
        float hz = z * sWr[32 + lane];           // W2
#pragma unroll
        for (int o = 16; o; o >>= 1) hz += __shfl_xor_sync(FULL, hz, o);
        if (lane == 0) out[n] = hz + sWr[64];
    }
}

// ---------------- gene fused mega-tile (96 KB smem) ----------------
__global__ void lin_gene_kernel(const float* __restrict__ agg,
                                const float* __restrict__ h,
                                __half* __restrict__ h16,
                                const float* __restrict__ convWl,
                                const float* __restrict__ convbl,
                                const float* __restrict__ convWr,
                                const float* __restrict__ gamma,
                                const float* __restrict__ beta) {
    extern __shared__ float sm[];
    float* sWa = sm;            // Wl1
    float* sWb = sm + 4096;     // Wl3
    float* sWc = sm + 8192;     // Wr1+Wr3
    float* sTa = sm + 12288;    // A1
    float* sTb = sm + 16384;    // A3
    float* sTc = sm + 20480;    // R

    const float* Wl1 = convWl + (size_t)1 * HID * HID;
    const float* Wl3 = convWl + (size_t)3 * HID * HID;
    const float* Wr1 = convWr + (size_t)1 * HID * HID;
    const float* Wr3 = convWr + (size_t)3 * HID * HID;
    for (int i = threadIdx.x; i < 4096; i += 256) {
        sWa[i] = Wl1[i];
        sWb[i] = Wl3[i];
        sWc[i] = Wr1[i] + Wr3[i];
    }
    int tx = threadIdx.x & 15;
    int ty = threadIdx.x >> 4;
    int j0 = tx * 4;
    int nb = ty * 4;
    float4 b1 = *(const float4*)(convbl + HID + j0);
    float4 b3 = *(const float4*)(convbl + 3 * HID + j0);
    float4 bias = make_float4(b1.x + b3.x, b1.y + b3.y, b1.z + b3.z, b1.w + b3.w);

    int n0 = blockIdx.x * 64;
    for (int i = threadIdx.x; i < 64 * 16; i += 256) {
        int nn = i >> 4, q = i & 15;
        int n = n0 + nn;
        float4 v1 = make_float4(0.f, 0.f, 0.f, 0.f), v3 = v1, vr = v1;
        if (n < NG) {
            v1 = ((const float4*)(agg + (size_t)(A1 + n) * HID))[q];
            v3 = ((const float4*)(agg + (size_t)(A3 + n) * HID))[q];
            vr = ((const float4*)(h + (size_t)n * HID))[q];
        }
        *(float4*)&sTa[nn * 64 + q * 4] = v1;
        *(float4*)&sTb[nn * 64 + q * 4] = v3;
        *(float4*)&sTc[nn * 64 + q * 4] = vr;
    }
    __syncthreads();

    float acc[4][4];
#pragma unroll
    for (int i = 0; i < 4; i++) {
        acc[i][0] = bias.x; acc[i][1] = bias.y; acc[i][2] = bias.z; acc[i][3] = bias.w;
    }
#pragma unroll 4
    for (int k = 0; k < 64; k++) {
        float4 wa = *(const float4*)&sWa[k * 64 + j0];
        float4 wb = *(const float4*)&sWb[k * 64 + j0];
        float4 wc = *(const float4*)&sWc[k * 64 + j0];
#pragma unroll
        for (int i = 0; i < 4; i++) {
            float a1 = sTa[(nb + i) * 64 + k];
            float a3 = sTb[(nb + i) * 64 + k];
            float r  = sTc[(nb + i) * 64 + k];
            acc[i][0] += a1 * wa.x + a3 * wb.x + r * wc.x;
            acc[i][1] += a1 * wa.y + a3 * wb.y + r * wc.y;
            acc[i][2] += a1 * wa.z + a3 * wb.z + r * wc.z;
            acc[i][3] += a1 * wa.w + a3 * wb.w + r * wc.w;
        }
    }

    float4 gm = *(const float4*)(gamma + j0);
    float4 bt = *(const float4*)(beta + j0);
#pragma unroll
    for (int i = 0; i < 4; i++) {
        int n = n0 + nb + i;
        float e0 = acc[i][0] + sTc[(nb + i) * 64 + j0];
        float e1 = acc[i][1] + sTc[(nb + i) * 64 + j0 + 1];
        float e2 = acc[i][2] + sTc[(nb + i) * 64 + j0 + 2];
        float e3 = acc[i][3] + sTc[(nb + i) * 64 + j0 + 3];
        float s = e0 + e1 + e2 + e3;
#pragma unroll
        for (int o = 1; o < 16; o <<= 1) s += __shfl_xor_sync(FULL, s, o);
        float mean = s * (1.f / 64.f);
        float d0 = e0 - mean, d1 = e1 - mean, d2 = e2 - mean, d3 = e3 - mean;
        float v = d0 * d0 + d1 * d1 + d2 * d2 + d3 * d3;
#pragma unroll
        for (int o = 1; o < 16; o <<= 1) v += __shfl_xor_sync(FULL, v, o);
        float rstd = rsqrtf(v * (1.f / 64.f) + 1e-5f);
        if (n < NG) {
            __half2* hp = (__half2*)(h16 + (size_t)n * HID + j0);
            hp[0] = __floats2half2_rn(elu1(d0 * rstd * gm.x + bt.x),
                                      elu1(d1 * rstd * gm.y + bt.y));
            hp[1] = __floats2half2_rn(elu1(d2 * rstd * gm.z + bt.z),
                                      elu1(d3 * rstd * gm.w + bt.w));
        }
    }
}

// ---------------- host launcher ----------------
static inline int cdiv(long long a, long long b) { return (int)((a + b - 1) / b); }

extern "C" void kernel_launch(void* const* d_in, const int* in_sizes, int n_in,
                              void* d_out, int out_size) {
    const float* x_gene = (const float*)d_in[0];
    const float* x_pat  = (const float*)d_in[1];
    const float* x_grp  = (const float*)d_in[2];
    const int* src0 = (const int*)d_in[3];
    const int* dst0 = (const int*)d_in[4];
    const int* src1 = (const int*)d_in[5];
    const int* dst1 = (const int*)d_in[6];
    // d_in[7], d_in[8]: src2/dst2 — dead for the output
    const int* src3 = (const int*)d_in[9];
    const int* dst3 = (const int*)d_in[10];
    const float* encGW = (const float*)d_in[11];
    const float* encGb = (const float*)d_in[12];
    const float* encPW = (const float*)d_in[13];
    const float* encPb = (const float*)d_in[14];
    const float* encMW = (const float*)d_in[15];
    const float* encMb = (const float*)d_in[16];
    const float* convWl = (const float*)d_in[17];   // [2,4,64,64]
    const float* convbl = (const float*)d_in[18];   // [2,4,64]
    const float* convWr = (const float*)d_in[19];   // [2,4,64,64]
    const float* lnG = (const float*)d_in[20];      // [2,3,64]
    const float* lnB = (const float*)d_in[21];
    const float* coxW1 = (const float*)d_in[22];
    const float* coxb1 = (const float*)d_in[23];
    const float* coxW2 = (const float*)d_in[24];
    const float* coxb2 = (const float*)d_in[25];
    float* out = (float*)d_out;

    const int E = in_sizes[3];

    float *hbuf, *aggbuf;
    __half* h16buf;
    cudaGetSymbolAddress((void**)&hbuf,   g_h);
    cudaGetSymbolAddress((void**)&h16buf, g_h16);
    cudaGetSymbolAddress((void**)&aggbuf, g_agg);

    static const int PAT_SMEM  = 4 * 4096 * (int)sizeof(float);   // 64 KB
    static const int GENE_SMEM = 6 * 4096 * (int)sizeof(float);   // 96 KB
    cudaFuncSetAttribute(lin_pat_kernel,
                         cudaFuncAttributeMaxDynamicSharedMemorySize, PAT_SMEM);
    cudaFuncSetAttribute(lin_gene_kernel,
                         cudaFuncAttributeMaxDynamicSharedMemorySize, GENE_SMEM);

    // [1] merged encoders + degree counts
    int cntB = cdiv(3LL * E, 256);
    enc_count_kernel<<<ENCB + cntB, 256>>>(
        x_gene, x_pat, x_grp, encGW, encGb, encPW, encPb, encMW, encMb,
        hbuf, h16buf, dst0, dst1, dst3, E);

    // [2-4] scan + fill
    scanA_kernel<<<NBTOT, 256>>>();
    scanC_kernel<<<NBTOT, 256>>>(E);
    fill_all_kernel<<<cdiv(3LL * E, 256), 256>>>(src0, dst0, src1, dst1, src3, dst3, E);

    // [5-7] layer 1: pull e0,e1,e3; gene mega-tile (h16); patient fused LN (fp32)
    pull_all_kernel<<<cdiv((long long)NSEG1 * 32, 256), 256>>>(h16buf, aggbuf, NSEG1);
    lin_gene_kernel<<<T1, 256, GENE_SMEM>>>(
        aggbuf, hbuf, h16buf, convWl, convbl, convWr, lnG, lnB);
    lin_pat_kernel<<<T0, 256, PAT_SMEM>>>(
        aggbuf, hbuf, convWl, convbl, convWr, lnG + HID, lnB + HID,
        coxW1, coxb1, coxW2, coxb2, out, 0);

    // [8-9] layer 2: pull e0; patient fused LN + cox (writes out directly)
    pull_all_kernel<<<cdiv((long long)NP * 32, 256), 256>>>(h16buf, aggbuf, NP);
    lin_pat_kernel<<<T0, 256, PAT_SMEM>>>(
        aggbuf, hbuf,
        convWl + (size_t)4 * HID * HID,
        convbl + (size_t)4 * HID,
        convWr + (size_t)4 * HID * HID,
        lnG + (size_t)3 * HID + HID,
        lnB + (size_t)3 * HID + HID,
        coxW1, coxb1, coxW2, coxb2, out, 1);
}

// round 16
// speedup vs baseline: 1.1803x; 1.0903x over previous
#include <cuda_runtime.h>
#include <cuda_bf16.h>
#include <cuda_fp16.h>
#include <math.h>

#define NG 20000
#define NP 100000
#define NM 5000
#define NTOT (NG + NP + NM)
#define HID 64
#define EMAX 1000000
#define FULL 0xFFFFFFFFu

// live edge types (orig ids): 0: gene->patient, 1: patient->gene, 2(orig 3): group->gene
// segment layout for agg: e0 | e1 | e3   (layer-2 pull uses a second bank)
#define A0 0
#define A1 NP
#define A3 (NP + NG)
#define NSEG1 (NP + 2 * NG)
// tiles
#define T0 ((NP + 63) / 64)
#define T1 ((NG + 63) / 64)
// encoder blocks in the merged enc+count launch
#define ENCB ((NTOT * HID + 255) / 256)
// scan chunking
#define SCH 1024
#define NB0 ((NP + SCH - 1) / SCH)
#define NB1 ((NG + SCH - 1) / SCH)
#define NB3 NB1
#define NBTOT (NB0 + NB1 + NB3)

// ---------------- scratch (static device globals; no allocs) ----------------
__device__ float  g_h  [NTOT * HID];               // fp32 master [gene|patient|group]
__device__ __align__(16) __half g_h16[NTOT * HID]; // fp16 gather mirror
__device__ float  g_agg[(NSEG1 + NP) * HID];       // bank0: layer1 (e0|e1|e3); bank1: layer2 e0
__device__ int    g_cnt[3][NP];      // zero at load; scanC restores zeros each call
__device__ int    g_off[3][NP + 1];
__device__ int    g_rank[3][EMAX];   // per-edge rank within its dst (from count atomic)
__device__ int    g_col[3][EMAX];
__device__ int    g_part[NBTOT];

#define OFF_GENE 0
#define OFF_PAT  (NG * HID)
#define OFF_GRP  ((NG + NP) * HID)

__device__ __forceinline__ float elu1(float x) { return x > 0.f ? x : expm1f(x); }

__constant__ int c_Ns[3] = { NP, NG, NG };

__device__ __forceinline__ void decode_scan_block(int b, int& t, int& c) {
    if      (b < NB0)       { t = 0; c = b; }
    else if (b < NB0 + NB1) { t = 1; c = b - NB0; }
    else                    { t = 2; c = b - NB0 - NB1; }
}

// ---------------- merged encoder + degree count (stores rank) ----------------
__global__ void enc_count_kernel(const float* __restrict__ x_gene,
                                 const float* __restrict__ x_pat,
                                 const float* __restrict__ x_grp,
                                 const float* __restrict__ Wg, const float* __restrict__ bg,
                                 const float* __restrict__ Wp, const float* __restrict__ bp,
                                 const float* __restrict__ Wm, const float* __restrict__ bm,
                                 float* __restrict__ h, __half* __restrict__ h16,
                                 const int* __restrict__ d0, const int* __restrict__ d1,
                                 const int* __restrict__ d3, int E) {
    if (blockIdx.x < ENCB) {
        int idx = blockIdx.x * blockDim.x + threadIdx.x;
        if (idx >= NTOT * HID) return;
        int n = idx >> 6;
        int j = idx & 63;
        const float* x; const float* W; const float* b; int K; int row; bool wf32;
        if (n < NG)           { x = x_gene; W = Wg; b = bg; K = 11; row = n;           wf32 = true; }
        else if (n < NG + NP) { x = x_pat;  W = Wp; b = bp; K = 3;  row = n - NG;      wf32 = true; }
        else                  { x = x_grp;  W = Wm; b = bm; K = 4;  row = n - NG - NP; wf32 = false; }
        float acc = b[j];
        for (int k = 0; k < K; k++)
            acc += x[row * K + k] * W[k * HID + j];
        float y = elu1(acc);
        if (wf32) h[idx] = y;
        h16[idx] = __float2half(y);
    } else {
        int i = (blockIdx.x - ENCB) * blockDim.x + threadIdx.x;
        if (i >= 3 * E) return;
        int t = (i >= E) + (i >= 2 * E);
        int j = i - t * E;
        const int* d = (t == 0) ? d0 : (t == 1) ? d1 : d3;
        int r = atomicAdd(&g_cnt[t][d[j]], 1);
        g_rank[t][j] = r;
    }
}

// ---------------- CSR scan ----------------
__global__ void scanA_kernel() {
    int t, c;
    decode_scan_block(blockIdx.x, t, c);
    int N = c_Ns[t];
    const int* cnt = g_cnt[t];
    int base = c * SCH + threadIdx.x * 4;
    int s = 0;
#pragma unroll
    for (int k = 0; k < 4; k++) {
        int i = base + k;
        if (i < N) s += cnt[i];
    }
    __shared__ int wsum[8];
    int lane = threadIdx.x & 31, wid = threadIdx.x >> 5;
#pragma unroll
    for (int o = 16; o; o >>= 1) s += __shfl_xor_sync(FULL, s, o);
    if (lane == 0) wsum[wid] = s;
    __syncthreads();
    if (threadIdx.x == 0) {
        int tot = 0;
#pragma unroll
        for (int w = 0; w < 8; w++) tot += wsum[w];
        g_part[blockIdx.x] = tot;
    }
}

__global__ void scanC_kernel(int E) {
    int t, c;
    decode_scan_block(blockIdx.x, t, c);
    int N = c_Ns[t];
    int* cnt = g_cnt[t];
    int* off = g_off[t];

    __shared__ int s_carry;
    int lane = threadIdx.x & 31, wid = threadIdx.x >> 5;
    if (wid == 0) {
        int pb = (t == 0) ? 0 : (t == 1) ? NB0 : NB0 + NB1;
        int sum = 0;
        for (int i = lane; i < c; i += 32) sum += g_part[pb + i];
#pragma unroll
        for (int o = 16; o; o >>= 1) sum += __shfl_xor_sync(FULL, sum, o);
        if (lane == 0) s_carry = sum;
    }
    __syncthreads();
    int carry = s_carry;

    int base = c * SCH + threadIdx.x * 4;
    int v[4];
    int tsum = 0;
#pragma unroll
    for (int k = 0; k < 4; k++) {
        int i = base + k;
        v[k] = (i < N) ? cnt[i] : 0;
        tsum += v[k];
    }
    __shared__ int wsum[8];
    int x = tsum;
#pragma unroll
    for (int o = 1; o < 32; o <<= 1) { int tt = __shfl_up_sync(FULL, x, o); if (lane >= o) x += tt; }
    if (lane == 31) wsum[wid] = x;
    __syncthreads();
    if (wid == 0 && lane < 8) {
        int w = wsum[lane];
#pragma unroll
        for (int o = 1; o < 8; o <<= 1) { int tt = __shfl_up_sync(0xFFu, w, o); if (lane >= o) w += tt; }
        wsum[lane] = w;
    }
    __syncthreads();
    int excl = (x - tsum) + (wid > 0 ? wsum[wid - 1] : 0) + carry;
#pragma unroll
    for (int k = 0; k < 4; k++) {
        int i = base + k;
        if (i < N) { off[i] = excl; cnt[i] = 0; }   // restore zero invariant
        excl += v[k];
    }
    if (threadIdx.x == 0 && c == (N + SCH - 1) / SCH - 1) off[N] = E;
}

// ---------------- atomic-free CSR fill (uses precomputed ranks) ----------------
__global__ void fill_all_kernel(const int* __restrict__ s0, const int* __restrict__ d0,
                                const int* __restrict__ s1, const int* __restrict__ d1,
                                const int* __restrict__ s3, const int* __restrict__ d3,
                                int E) {
    int i = blockIdx.x * blockDim.x + threadIdx.x;
    if (i >= 3 * E) return;
    int t = (i >= E) + (i >= 2 * E);
    int j = i - t * E;
    const int* s = (t == 0) ? s0 : (t == 1) ? s1 : s3;
    const int* d = (t == 0) ? d0 : (t == 1) ? d1 : d3;
    int p = g_off[t][d[j]] + g_rank[t][j];
    g_col[t][p] = s[j];
}

// ---------------- pull aggregation (mean), fp16 gather ----------------
__global__ void pull_all_kernel(const __half* __restrict__ h16buf,
                                float* __restrict__ agg, int nseg) {
    int warp = (blockIdx.x * blockDim.x + threadIdx.x) >> 5;
    int lane = threadIdx.x & 31;
    if (warp >= nseg) return;

    int t, n;
    if      (warp < A1) { t = 0; n = warp; }
    else if (warp < A3) { t = 1; n = warp - A1; }
    else                { t = 2; n = warp - A3; }

    const int srcoff_tab[3] = { OFF_GENE, OFF_PAT, OFF_GRP };
    const __half* h_src = h16buf + srcoff_tab[t];
    const int* off = g_off[t];
    const int* col = g_col[t];

    const int qr = lane >> 3;
    const int q8 = lane & 7;

    int o0 = off[n], o1 = off[n + 1];
    float2 acc[4];
#pragma unroll
    for (int k = 0; k < 4; k++) acc[k] = make_float2(0.f, 0.f);

    for (int base = o0; base < o1; base += 32) {
        int idx = (base + lane < o1) ? col[base + lane] : 0;
        int m = min(32, o1 - base);
#pragma unroll 4
        for (int j = 0; j < m; j += 4) {
            int jj = j + qr;
            int s = __shfl_sync(FULL, idx, jj & 31);
            if (jj < m) {
                float4 raw = ((const float4*)(h_src + (size_t)s * HID))[q8];
                const __half2* hp = (const __half2*)&raw;
#pragma unroll
                for (int k = 0; k < 4; k++) {
                    float2 f = __half22float2(hp[k]);
                    acc[k].x += f.x;
                    acc[k].y += f.y;
                }
            }
        }
    }
#pragma unroll
    for (int k = 0; k < 4; k++) {
        acc[k].x += __shfl_xor_sync(FULL, acc[k].x, 8);
        acc[k].y += __shfl_xor_sync(FULL, acc[k].y, 8);
        acc[k].x += __shfl_xor_sync(FULL, acc[k].x, 16);
        acc[k].y += __shfl_xor_sync(FULL, acc[k].y, 16);
    }
    if (qr == 0) {
        float inv = 1.f / fmaxf((float)(o1 - o0), 1.f);
        float4 w0 = make_float4(acc[0].x * inv, acc[0].y * inv, acc[1].x * inv, acc[1].y * inv);
        float4 w1 = make_float4(acc[2].x * inv, acc[2].y * inv, acc[3].x * inv, acc[3].y * inv);
        float4* dstp = (float4*)&agg[(size_t)warp * HID + q8 * 8];
        dstp[0] = w0;
        dstp[1] = w1;
    }
}

// ---------------- patient fused linear + residual + LN + ELU [+ cox] (64 KB) ----
__global__ void lin_pat_kernel(const float* __restrict__ agg,
                               float* __restrict__ h,
                               const float* __restrict__ Wl,
                               const float* __restrict__ bl,
                               const float* __restrict__ Wr,
                               const float* __restrict__ gamma,
                               const float* __restrict__ beta,
                               const float* __restrict__ cW1,
                               const float* __restrict__ cb1,
                               const float* __restrict__ cW2,
                               const float* __restrict__ cb2,
                               float* __restrict__ out,
                               int do_cox) {
    extern __shared__ float sm[];
    float* sWl = sm;
    float* sWr = sm + 4096;
    float* sA  = sm + 8192;
    float* sR  = sm + 12288;

    for (int i = threadIdx.x; i < 4096; i += 256) {
        sWl[i] = Wl[i];
        sWr[i] = Wr[i];
    }
    int tx = threadIdx.x & 15;
    int ty = threadIdx.x >> 4;
    int j0 = tx * 4;
    int nb = ty * 4;
    float4 bias = *(const float4*)(bl + j0);

    int n0 = blockIdx.x * 64;
    const float* h_root = h + OFF_PAT;
    for (int i = threadIdx.x; i < 64 * 16; i += 256) {
        int nn = i >> 4, q = i & 15;
        int n = n0 + nn;
        float4 va = make_float4(0.f, 0.f, 0.f, 0.f), vr = va;
        if (n < NP) {
            va = ((const float4*)(agg + (size_t)n * HID))[q];
            vr = ((const float4*)(h_root + (size_t)n * HID))[q];
        }
        *(float4*)&sA[nn * 64 + q * 4] = va;
        *(float4*)&sR[nn * 64 + q * 4] = vr;
    }
    __syncthreads();

    float acc[4][4];
#pragma unroll
    for (int i = 0; i < 4; i++) {
        acc[i][0] = bias.x; acc[i][1] = bias.y; acc[i][2] = bias.z; acc[i][3] = bias.w;
    }
#pragma unroll 8
    for (int k = 0; k < 64; k++) {
        float4 wa = *(const float4*)&sWl[k * 64 + j0];
        float4 wb = *(const float4*)&sWr[k * 64 + j0];
#pragma unroll
        for (int i = 0; i < 4; i++) {
            float a = sA[(nb + i) * 64 + k];
            float r = sR[(nb + i) * 64 + k];
            acc[i][0] += a * wa.x + r * wb.x;
            acc[i][1] += a * wa.y + r * wb.y;
            acc[i][2] += a * wa.z + r * wb.z;
            acc[i][3] += a * wa.w + r * wb.w;
        }
    }

    float4 gm = *(const float4*)(gamma + j0);
    float4 bt = *(const float4*)(beta + j0);
#pragma unroll
    for (int i = 0; i < 4; i++) {
        int n = n0 + nb + i;
        float e0 = acc[i][0] + sR[(nb + i) * 64 + j0];
        float e1 = acc[i][1] + sR[(nb + i) * 64 + j0 + 1];
        float e2 = acc[i][2] + sR[(nb + i) * 64 + j0 + 2];
        float e3 = acc[i][3] + sR[(nb + i) * 64 + j0 + 3];
        float s = e0 + e1 + e2 + e3;
#pragma unroll
        for (int o = 1; o < 16; o <<= 1) s += __shfl_xor_sync(FULL, s, o);
        float mean = s * (1.f / 64.f);
        float d0 = e0 - mean, d1 = e1 - mean, d2 = e2 - mean, d3 = e3 - mean;
        float v = d0 * d0 + d1 * d1 + d2 * d2 + d3 * d3;
#pragma unroll
        for (int o = 1; o < 16; o <<= 1) v += __shfl_xor_sync(FULL, v, o);
        float rstd = rsqrtf(v * (1.f / 64.f) + 1e-5f);
        float y0 = elu1(d0 * rstd * gm.x + bt.x);
        float y1 = elu1(d1 * rstd * gm.y + bt.y);
        float y2 = elu1(d2 * rstd * gm.z + bt.z);
        float y3 = elu1(d3 * rstd * gm.w + bt.w);
        if (do_cox) {
            *(float4*)&sA[(nb + i) * 64 + j0] = make_float4(y0, y1, y2, y3);
        } else if (n < NP) {
            *(float4*)(h + OFF_PAT + (size_t)n * HID + j0) =
                make_float4(y0, y1, y2, y3);
        }
    }

    if (!do_cox) return;

    // ---- in-block cox head ----
    __syncthreads();
    for (int i = threadIdx.x; i < HID * 32; i += 256) sWl[i] = cW1[i];
    if (threadIdx.x < 32) {
        sWr[threadIdx.x] = cb1[threadIdx.x];
        sWr[32 + threadIdx.x] = cW2[threadIdx.x];
    }
    if (threadIdx.x == 0) sWr[64] = cb2[0];
    __syncthreads();

    int wid = threadIdx.x >> 5;
    int lane = threadIdx.x & 31;
    for (int r = wid * 8; r < wid * 8 + 8; r++) {
        int n = n0 + r;
        if (n >= NP) continue;
        float z = sWr[lane];
        const float* yrow = &sA[r * 64];
#pragma unroll 8
        for (int k = 0; k < 64; k++) {
            z += yrow[k] * sWl[k * 32 + lane];
        }
        z = elu1(z);
        float hz = z * sWr[32 + lane];
#pragma unroll
        for (int o = 16; o; o >>= 1) hz += __shfl_xor_sync(FULL, hz, o);
        if (lane == 0) out[n] = hz + sWr[64];
    }
}

// ---------------- gene fused mega-tile (96 KB smem) ----------------
__global__ void lin_gene_kernel(const float* __restrict__ agg,
                                const float* __restrict__ h,
                                __half* __restrict__ h16,
                                const float* __restrict__ convWl,
                                const float* __restrict__ convbl,
                                const float* __restrict__ convWr,
                                const float* __restrict__ gamma,
                                const float* __restrict__ beta) {
    extern __shared__ float sm[];
    float* sWa = sm;
    float* sWb = sm + 4096;
    float* sWc = sm + 8192;
    float* sTa = sm + 12288;
    float* sTb = sm + 16384;
    float* sTc = sm + 20480;

    const float* Wl1 = convWl + (size_t)1 * HID * HID;
    const float* Wl3 = convWl + (size_t)3 * HID * HID;
    const float* Wr1 = convWr + (size_t)1 * HID * HID;
    const float* Wr3 = convWr + (size_t)3 * HID * HID;
    for (int i = threadIdx.x; i < 4096; i += 256) {
        sWa[i] = Wl1[i];
        sWb[i] = Wl3[i];
        sWc[i] = Wr1[i] + Wr3[i];
    }
    int tx = threadIdx.x & 15;
    int ty = threadIdx.x >> 4;
    int j0 = tx * 4;
    int nb = ty * 4;
    float4 b1 = *(const float4*)(convbl + HID + j0);
    float4 b3 = *(const float4*)(convbl + 3 * HID + j0);
    float4 bias = make_float4(b1.x + b3.x, b1.y + b3.y, b1.z + b3.z, b1.w + b3.w);

    int n0 = blockIdx.x * 64;
    for (int i = threadIdx.x; i < 64 * 16; i += 256) {
        int nn = i >> 4, q = i & 15;
        int n = n0 + nn;
        float4 v1 = make_float4(0.f, 0.f, 0.f, 0.f), v3 = v1, vr = v1;
        if (n < NG) {
            v1 = ((const float4*)(agg + (size_t)(A1 + n) * HID))[q];
            v3 = ((const float4*)(agg + (size_t)(A3 + n) * HID))[q];
            vr = ((const float4*)(h + (size_t)n * HID))[q];
        }
        *(float4*)&sTa[nn * 64 + q * 4] = v1;
        *(float4*)&sTb[nn * 64 + q * 4] = v3;
        *(float4*)&sTc[nn * 64 + q * 4] = vr;
    }
    __syncthreads();

    float acc[4][4];
#pragma unroll
    for (int i = 0; i < 4; i++) {
        acc[i][0] = bias.x; acc[i][1] = bias.y; acc[i][2] = bias.z; acc[i][3] = bias.w;
    }
#pragma unroll 4
    for (int k = 0; k < 64; k++) {
        float4 wa = *(const float4*)&sWa[k * 64 + j0];
        float4 wb = *(const float4*)&sWb[k * 64 + j0];
        float4 wc = *(const float4*)&sWc[k * 64 + j0];
#pragma unroll
        for (int i = 0; i < 4; i++) {
            float a1 = sTa[(nb + i) * 64 + k];
            float a3 = sTb[(nb + i) * 64 + k];
            float r  = sTc[(nb + i) * 64 + k];
            acc[i][0] += a1 * wa.x + a3 * wb.x + r * wc.x;
            acc[i][1] += a1 * wa.y + a3 * wb.y + r * wc.y;
            acc[i][2] += a1 * wa.z + a3 * wb.z + r * wc.z;
            acc[i][3] += a1 * wa.w + a3 * wb.w + r * wc.w;
        }
    }

    float4 gm = *(const float4*)(gamma + j0);
    float4 bt = *(const float4*)(beta + j0);
#pragma unroll
    for (int i = 0; i < 4; i++) {
        int n = n0 + nb + i;
        float e0 = acc[i][0] + sTc[(nb + i) * 64 + j0];
        float e1 = acc[i][1] + sTc[(nb + i) * 64 + j0 + 1];
        float e2 = acc[i][2] + sTc[(nb + i) * 64 + j0 + 2];
        float e3 = acc[i][3] + sTc[(nb + i) * 64 + j0 + 3];
        float s = e0 + e1 + e2 + e3;
#pragma unroll
        for (int o = 1; o < 16; o <<= 1) s += __shfl_xor_sync(FULL, s, o);
        float mean = s * (1.f / 64.f);
        float d0 = e0 - mean, d1 = e1 - mean, d2 = e2 - mean, d3 = e3 - mean;
        float v = d0 * d0 + d1 * d1 + d2 * d2 + d3 * d3;
#pragma unroll
        for (int o = 1; o < 16; o <<= 1) v += __shfl_xor_sync(FULL, v, o);
        float rstd = rsqrtf(v * (1.f / 64.f) + 1e-5f);
        if (n < NG) {
            __half2* hp = (__half2*)(h16 + (size_t)n * HID + j0);
            hp[0] = __floats2half2_rn(elu1(d0 * rstd * gm.x + bt.x),
                                      elu1(d1 * rstd * gm.y + bt.y));
            hp[1] = __floats2half2_rn(elu1(d2 * rstd * gm.z + bt.z),
                                      elu1(d3 * rstd * gm.w + bt.w));
        }
    }
}

// ---------------- host launcher ----------------
static inline int cdiv(long long a, long long b) { return (int)((a + b - 1) / b); }

extern "C" void kernel_launch(void* const* d_in, const int* in_sizes, int n_in,
                              void* d_out, int out_size) {
    const float* x_gene = (const float*)d_in[0];
    const float* x_pat  = (const float*)d_in[1];
    const float* x_grp  = (const float*)d_in[2];
    const int* src0 = (const int*)d_in[3];
    const int* dst0 = (const int*)d_in[4];
    const int* src1 = (const int*)d_in[5];
    const int* dst1 = (const int*)d_in[6];
    // d_in[7], d_in[8]: src2/dst2 — dead for the output
    const int* src3 = (const int*)d_in[9];
    const int* dst3 = (const int*)d_in[10];
    const float* encGW = (const float*)d_in[11];
    const float* encGb = (const float*)d_in[12];
    const float* encPW = (const float*)d_in[13];
    const float* encPb = (const float*)d_in[14];
    const float* encMW = (const float*)d_in[15];
    const float* encMb = (const float*)d_in[16];
    const float* convWl = (const float*)d_in[17];   // [2,4,64,64]
    const float* convbl = (const float*)d_in[18];   // [2,4,64]
    const float* convWr = (const float*)d_in[19];   // [2,4,64,64]
    const float* lnG = (const float*)d_in[20];      // [2,3,64]
    const float* lnB = (const float*)d_in[21];
    const float* coxW1 = (const float*)d_in[22];
    const float* coxb1 = (const float*)d_in[23];
    const float* coxW2 = (const float*)d_in[24];
    const float* coxb2 = (const float*)d_in[25];
    float* out = (float*)d_out;

    const int E = in_sizes[3];

    float *hbuf, *aggbuf;
    __half* h16buf;
    cudaGetSymbolAddress((void**)&hbuf,   g_h);
    cudaGetSymbolAddress((void**)&h16buf, g_h16);
    cudaGetSymbolAddress((void**)&aggbuf, g_agg);
    float* agg2 = aggbuf + (size_t)NSEG1 * HID;   // layer-2 e0 bank

    static const int PAT_SMEM  = 4 * 4096 * (int)sizeof(float);   // 64 KB
    static const int GENE_SMEM = 6 * 4096 * (int)sizeof(float);   // 96 KB
    cudaFuncSetAttribute(lin_pat_kernel,
                         cudaFuncAttributeMaxDynamicSharedMemorySize, PAT_SMEM);
    cudaFuncSetAttribute(lin_gene_kernel,
                         cudaFuncAttributeMaxDynamicSharedMemorySize, GENE_SMEM);

    // one-time host objects (created on the correctness call, outside graph capture;
    // every call issues the identical launch/event sequence — work is deterministic)
    static cudaStream_t s_side = nullptr;
    static cudaEvent_t ev_fork = nullptr, ev_join = nullptr;
    if (s_side == nullptr) {
        cudaStreamCreateWithFlags(&s_side, cudaStreamNonBlocking);
        cudaEventCreateWithFlags(&ev_fork, cudaEventDisableTiming);
        cudaEventCreateWithFlags(&ev_join, cudaEventDisableTiming);
    }

    // [1] merged encoders + degree counts (rank-storing)
    int cntB = cdiv(3LL * E, 256);
    enc_count_kernel<<<ENCB + cntB, 256>>>(
        x_gene, x_pat, x_grp, encGW, encGb, encPW, encPb, encMW, encMb,
        hbuf, h16buf, dst0, dst1, dst3, E);

    // [2-4] scan + atomic-free fill
    scanA_kernel<<<NBTOT, 256>>>();
    scanC_kernel<<<NBTOT, 256>>>(E);
    fill_all_kernel<<<cdiv(3LL * E, 256), 256>>>(src0, dst0, src1, dst1, src3, dst3, E);

    // [5] layer-1 pull (e0, e1, e3)
    pull_all_kernel<<<cdiv((long long)NSEG1 * 32, 256), 256>>>(h16buf, aggbuf, NSEG1);

    // fork: side stream runs gene linear then layer-2 pull (into agg2);
    // main stream runs patient L1 linear concurrently.
    cudaEventRecord(ev_fork, 0);
    cudaStreamWaitEvent(s_side, ev_fork, 0);
    lin_gene_kernel<<<T1, 256, GENE_SMEM, s_side>>>(
        aggbuf, hbuf, h16buf, convWl, convbl, convWr, lnG, lnB);
    pull_all_kernel<<<cdiv((long long)NP * 32, 256), 256, 0, s_side>>>(h16buf, agg2, NP);
    cudaEventRecord(ev_join, s_side);

    lin_pat_kernel<<<T0, 256, PAT_SMEM>>>(
        aggbuf, hbuf, convWl, convbl, convWr, lnG + HID, lnB + HID,
        coxW1, coxb1, coxW2, coxb2, out, 0);

    // join, then layer-2 patient linear + cox
    cudaStreamWaitEvent(0, ev_join, 0);
    lin_pat_kernel<<<T0, 256, PAT_SMEM>>>(
        agg2, hbuf,
        convWl + (size_t)4 * HID * HID,
        convbl + (size_t)4 * HID,
        convWr + (size_t)4 * HID * HID,
        lnG + (size_t)3 * HID + HID,
        lnB + (size_t)3 * HID + HID,
        coxW1, coxb1, coxW2, coxb2, out, 1);
}

// round 17
// speedup vs baseline: 1.1915x; 1.0095x over previous
#include <cuda_runtime.h>
#include <cuda_bf16.h>
#include <cuda_fp16.h>
#include <math.h>

#define NG 20000
#define NP 100000
#define NM 5000
#define NTOT (NG + NP + NM)
#define HID 64
#define EMAX 1000000
#define FULL 0xFFFFFFFFu

// live edge types (orig ids): 0: gene->patient, 1: patient->gene, 2(orig 3): group->gene
// segment layout for agg: e0 | e1 | e3   (layer-2 pull uses a second bank)
#define A0 0
#define A1 NP
#define A3 (NP + NG)
#define NSEG1 (NP + 2 * NG)
// tiles
#define T0 ((NP + 63) / 64)
#define T1 ((NG + 63) / 64)
// encoder blocks in the merged enc+count launch
#define ENCB ((NTOT * HID + 255) / 256)
// scan chunking
#define SCH 1024
#define NB0 ((NP + SCH - 1) / SCH)
#define NB1 ((NG + SCH - 1) / SCH)
#define NB3 NB1
#define NBTOT (NB0 + NB1 + NB3)

// ---------------- scratch (static device globals; no allocs) ----------------
__device__ float  g_h  [NTOT * HID];               // fp32 master [gene|patient|group]
__device__ __align__(16) __half g_h16 [NTOT * HID]; // fp16 mirror (layer-1 values)
__device__ __align__(16) __half g_h16b[NG * HID];   // gene layer-2 fp16 bank
__device__ float  g_agg[(NSEG1 + NP) * HID];       // bank0: layer1; bank1: layer2 e0
__device__ int    g_cnt[3][NP];      // zero at load; scanC restores zeros each call
__device__ int    g_off[3][NP + 1];
__device__ int    g_rank[3][EMAX];   // per-edge rank within its dst (from count atomic)
__device__ int    g_col[3][EMAX];
__device__ int    g_part[NBTOT];

#define OFF_GENE 0
#define OFF_PAT  (NG * HID)
#define OFF_GRP  ((NG + NP) * HID)

__device__ __forceinline__ float elu1(float x) { return x > 0.f ? x : expm1f(x); }

__constant__ int c_Ns[3] = { NP, NG, NG };

__device__ __forceinline__ void decode_scan_block(int b, int& t, int& c) {
    if      (b < NB0)       { t = 0; c = b; }
    else if (b < NB0 + NB1) { t = 1; c = b - NB0; }
    else                    { t = 2; c = b - NB0 - NB1; }
}

// ---------------- merged encoder + degree count (stores rank) ----------------
__global__ void enc_count_kernel(const float* __restrict__ x_gene,
                                 const float* __restrict__ x_pat,
                                 const float* __restrict__ x_grp,
                                 const float* __restrict__ Wg, const float* __restrict__ bg,
                                 const float* __restrict__ Wp, const float* __restrict__ bp,
                                 const float* __restrict__ Wm, const float* __restrict__ bm,
                                 float* __restrict__ h, __half* __restrict__ h16,
                                 const int* __restrict__ d0, const int* __restrict__ d1,
                                 const int* __restrict__ d3, int E) {
    if (blockIdx.x < ENCB) {
        int idx = blockIdx.x * blockDim.x + threadIdx.x;
        if (idx >= NTOT * HID) return;
        int n = idx >> 6;
        int j = idx & 63;
        const float* x; const float* W; const float* b; int K; int row; bool wf32;
        if (n < NG)           { x = x_gene; W = Wg; b = bg; K = 11; row = n;           wf32 = true; }
        else if (n < NG + NP) { x = x_pat;  W = Wp; b = bp; K = 3;  row = n - NG;      wf32 = true; }
        else                  { x = x_grp;  W = Wm; b = bm; K = 4;  row = n - NG - NP; wf32 = false; }
        float acc = b[j];
        for (int k = 0; k < K; k++)
            acc += x[row * K + k] * W[k * HID + j];
        float y = elu1(acc);
        if (wf32) h[idx] = y;
        h16[idx] = __float2half(y);
    } else {
        int i = (blockIdx.x - ENCB) * blockDim.x + threadIdx.x;
        if (i >= 3 * E) return;
        int t = (i >= E) + (i >= 2 * E);
        int j = i - t * E;
        const int* d = (t == 0) ? d0 : (t == 1) ? d1 : d3;
        int r = atomicAdd(&g_cnt[t][d[j]], 1);
        g_rank[t][j] = r;
    }
}

// ---------------- CSR scan ----------------
__global__ void scanA_kernel() {
    int t, c;
    decode_scan_block(blockIdx.x, t, c);
    int N = c_Ns[t];
    const int* cnt = g_cnt[t];
    int base = c * SCH + threadIdx.x * 4;
    int s = 0;
#pragma unroll
    for (int k = 0; k < 4; k++) {
        int i = base + k;
        if (i < N) s += cnt[i];
    }
    __shared__ int wsum[8];
    int lane = threadIdx.x & 31, wid = threadIdx.x >> 5;
#pragma unroll
    for (int o = 16; o; o >>= 1) s += __shfl_xor_sync(FULL, s, o);
    if (lane == 0) wsum[wid] = s;
    __syncthreads();
    if (threadIdx.x == 0) {
        int tot = 0;
#pragma unroll
        for (int w = 0; w < 8; w++) tot += wsum[w];
        g_part[blockIdx.x] = tot;
    }
}

__global__ void scanC_kernel(int E) {
    int t, c;
    decode_scan_block(blockIdx.x, t, c);
    int N = c_Ns[t];
    int* cnt = g_cnt[t];
    int* off = g_off[t];

    __shared__ int s_carry;
    int lane = threadIdx.x & 31, wid = threadIdx.x >> 5;
    if (wid == 0) {
        int pb = (t == 0) ? 0 : (t == 1) ? NB0 : NB0 + NB1;
        int sum = 0;
        for (int i = lane; i < c; i += 32) sum += g_part[pb + i];
#pragma unroll
        for (int o = 16; o; o >>= 1) sum += __shfl_xor_sync(FULL, sum, o);
        if (lane == 0) s_carry = sum;
    }
    __syncthreads();
    int carry = s_carry;

    int base = c * SCH + threadIdx.x * 4;
    int v[4];
    int tsum = 0;
#pragma unroll
    for (int k = 0; k < 4; k++) {
        int i = base + k;
        v[k] = (i < N) ? cnt[i] : 0;
        tsum += v[k];
    }
    __shared__ int wsum[8];
    int x = tsum;
#pragma unroll
    for (int o = 1; o < 32; o <<= 1) { int tt = __shfl_up_sync(FULL, x, o); if (lane >= o) x += tt; }
    if (lane == 31) wsum[wid] = x;
    __syncthreads();
    if (wid == 0 && lane < 8) {
        int w = wsum[lane];
#pragma unroll
        for (int o = 1; o < 8; o <<= 1) { int tt = __shfl_up_sync(0xFFu, w, o); if (lane >= o) w += tt; }
        wsum[lane] = w;
    }
    __syncthreads();
    int excl = (x - tsum) + (wid > 0 ? wsum[wid - 1] : 0) + carry;
#pragma unroll
    for (int k = 0; k < 4; k++) {
        int i = base + k;
        if (i < N) { off[i] = excl; cnt[i] = 0; }
        excl += v[k];
    }
    if (threadIdx.x == 0 && c == (N + SCH - 1) / SCH - 1) off[N] = E;
}

// ---------------- atomic-free CSR fill ----------------
__global__ void fill_all_kernel(const int* __restrict__ s0, const int* __restrict__ d0,
                                const int* __restrict__ s1, const int* __restrict__ d1,
                                const int* __restrict__ s3, const int* __restrict__ d3,
                                int E) {
    int i = blockIdx.x * blockDim.x + threadIdx.x;
    if (i >= 3 * E) return;
    int t = (i >= E) + (i >= 2 * E);
    int j = i - t * E;
    const int* s = (t == 0) ? s0 : (t == 1) ? s1 : s3;
    const int* d = (t == 0) ? d0 : (t == 1) ? d1 : d3;
    int p = g_off[t][d[j]] + g_rank[t][j];
    g_col[t][p] = s[j];
}

// ---------------- pull aggregation (mean), fp16 gather ----------------
// handles segment-space warps [warp_off, warp_off + nwarps); agg indexed by
// LOCAL warp id (so layer-2 bank works). h16base: source table base.
__global__ void pull_all_kernel(const __half* __restrict__ h16base,
                                float* __restrict__ agg, int warp_off, int nwarps) {
    int warp = (blockIdx.x * blockDim.x + threadIdx.x) >> 5;
    int lane = threadIdx.x & 31;
    if (warp >= nwarps) return;
    int gseg = warp + warp_off;

    int t, n;
    if      (gseg < A1) { t = 0; n = gseg; }
    else if (gseg < A3) { t = 1; n = gseg - A1; }
    else                { t = 2; n = gseg - A3; }

    const int srcoff_tab[3] = { OFF_GENE, OFF_PAT, OFF_GRP };
    const __half* h_src = h16base + srcoff_tab[t];
    const int* off = g_off[t];
    const int* col = g_col[t];

    const int qr = lane >> 3;
    const int q8 = lane & 7;

    int o0 = off[n], o1 = off[n + 1];
    float2 acc[4];
#pragma unroll
    for (int k = 0; k < 4; k++) acc[k] = make_float2(0.f, 0.f);

    for (int base = o0; base < o1; base += 32) {
        int idx = (base + lane < o1) ? col[base + lane] : 0;
        int m = min(32, o1 - base);
#pragma unroll 4
        for (int j = 0; j < m; j += 4) {
            int jj = j + qr;
            int s = __shfl_sync(FULL, idx, jj & 31);
            if (jj < m) {
                float4 raw = ((const float4*)(h_src + (size_t)s * HID))[q8];
                const __half2* hp = (const __half2*)&raw;
#pragma unroll
                for (int k = 0; k < 4; k++) {
                    float2 f = __half22float2(hp[k]);
                    acc[k].x += f.x;
                    acc[k].y += f.y;
                }
            }
        }
    }
#pragma unroll
    for (int k = 0; k < 4; k++) {
        acc[k].x += __shfl_xor_sync(FULL, acc[k].x, 8);
        acc[k].y += __shfl_xor_sync(FULL, acc[k].y, 8);
        acc[k].x += __shfl_xor_sync(FULL, acc[k].x, 16);
        acc[k].y += __shfl_xor_sync(FULL, acc[k].y, 16);
    }
    if (qr == 0) {
        float inv = 1.f / fmaxf((float)(o1 - o0), 1.f);
        float4 w0 = make_float4(acc[0].x * inv, acc[0].y * inv, acc[1].x * inv, acc[1].y * inv);
        float4 w1 = make_float4(acc[2].x * inv, acc[2].y * inv, acc[3].x * inv, acc[3].y * inv);
        float4* dstp = (float4*)&agg[(size_t)warp * HID + q8 * 8];
        dstp[0] = w0;
        dstp[1] = w1;
    }
}

// ---------------- patient fused linear + residual + LN + ELU [+ cox] (64 KB) ----
__global__ void lin_pat_kernel(const float* __restrict__ agg,
                               float* __restrict__ h,
                               const float* __restrict__ Wl,
                               const float* __restrict__ bl,
                               const float* __restrict__ Wr,
                               const float* __restrict__ gamma,
                               const float* __restrict__ beta,
                               const float* __restrict__ cW1,
                               const float* __restrict__ cb1,
                               const float* __restrict__ cW2,
                               const float* __restrict__ cb2,
                               float* __restrict__ out,
                               int do_cox) {
    extern __shared__ float sm[];
    float* sWl = sm;
    float* sWr = sm + 4096;
    float* sA  = sm + 8192;
    float* sR  = sm + 12288;

    for (int i = threadIdx.x; i < 4096; i += 256) {
        sWl[i] = Wl[i];
        sWr[i] = Wr[i];
    }
    int tx = threadIdx.x & 15;
    int ty = threadIdx.x >> 4;
    int j0 = tx * 4;
    int nb = ty * 4;
    float4 bias = *(const float4*)(bl + j0);

    int n0 = blockIdx.x * 64;
    const float* h_root = h + OFF_PAT;
    for (int i = threadIdx.x; i < 64 * 16; i += 256) {
        int nn = i >> 4, q = i & 15;
        int n = n0 + nn;
        float4 va = make_float4(0.f, 0.f, 0.f, 0.f), vr = va;
        if (n < NP) {
            va = ((const float4*)(agg + (size_t)n * HID))[q];
            vr = ((const float4*)(h_root + (size_t)n * HID))[q];
        }
        *(float4*)&sA[nn * 64 + q * 4] = va;
        *(float4*)&sR[nn * 64 + q * 4] = vr;
    }
    __syncthreads();

    float acc[4][4];
#pragma unroll
    for (int i = 0; i < 4; i++) {
        acc[i][0] = bias.x; acc[i][1] = bias.y; acc[i][2] = bias.z; acc[i][3] = bias.w;
    }
#pragma unroll 8
    for (int k = 0; k < 64; k++) {
        float4 wa = *(const float4*)&sWl[k * 64 + j0];
        float4 wb = *(const float4*)&sWr[k * 64 + j0];
#pragma unroll
        for (int i = 0; i < 4; i++) {
            float a = sA[(nb + i) * 64 + k];
            float r = sR[(nb + i) * 64 + k];
            acc[i][0] += a * wa.x + r * wb.x;
            acc[i][1] += a * wa.y + r * wb.y;
            acc[i][2] += a * wa.z + r * wb.z;
            acc[i][3] += a * wa.w + r * wb.w;
        }
    }

    float4 gm = *(const float4*)(gamma + j0);
    float4 bt = *(const float4*)(beta + j0);
#pragma unroll
    for (int i = 0; i < 4; i++) {
        int n = n0 + nb + i;
        float e0 = acc[i][0] + sR[(nb + i) * 64 + j0];
        float e1 = acc[i][1] + sR[(nb + i) * 64 + j0 + 1];
        float e2 = acc[i][2] + sR[(nb + i) * 64 + j0 + 2];
        float e3 = acc[i][3] + sR[(nb + i) * 64 + j0 + 3];
        float s = e0 + e1 + e2 + e3;
#pragma unroll
        for (int o = 1; o < 16; o <<= 1) s += __shfl_xor_sync(FULL, s, o);
        float mean = s * (1.f / 64.f);
        float d0 = e0 - mean, d1 = e1 - mean, d2 = e2 - mean, d3 = e3 - mean;
        float v = d0 * d0 + d1 * d1 + d2 * d2 + d3 * d3;
#pragma unroll
        for (int o = 1; o < 16; o <<= 1) v += __shfl_xor_sync(FULL, v, o);
        float rstd = rsqrtf(v * (1.f / 64.f) + 1e-5f);
        float y0 = elu1(d0 * rstd * gm.x + bt.x);
        float y1 = elu1(d1 * rstd * gm.y + bt.y);
        float y2 = elu1(d2 * rstd * gm.z + bt.z);
        float y3 = elu1(d3 * rstd * gm.w + bt.w);
        if (do_cox) {
            *(float4*)&sA[(nb + i) * 64 + j0] = make_float4(y0, y1, y2, y3);
        } else if (n < NP) {
            *(float4*)(h + OFF_PAT + (size_t)n * HID + j0) =
                make_float4(y0, y1, y2, y3);
        }
    }

    if (!do_cox) return;

    // ---- in-block cox head ----
    __syncthreads();
    for (int i = threadIdx.x; i < HID * 32; i += 256) sWl[i] = cW1[i];
    if (threadIdx.x < 32) {
        sWr[threadIdx.x] = cb1[threadIdx.x];
        sWr[32 + threadIdx.x] = cW2[threadIdx.x];
    }
    if (threadIdx.x == 0) sWr[64] = cb2[0];
    __syncthreads();

    int wid = threadIdx.x >> 5;
    int lane = threadIdx.x & 31;
    for (int r = wid * 8; r < wid * 8 + 8; r++) {
        int n = n0 + r;
        if (n >= NP) continue;
        float z = sWr[lane];
        const float* yrow = &sA[r * 64];
#pragma unroll 8
        for (int k = 0; k < 64; k++) {
            z += yrow[k] * sWl[k * 32 + lane];
        }
        z = elu1(z);
        float hz = z * sWr[32 + lane];
#pragma unroll
        for (int o = 16; o; o >>= 1) hz += __shfl_xor_sync(FULL, hz, o);
        if (lane == 0) out[n] = hz + sWr[64];
    }
}

// ---------------- gene fused mega-tile (96 KB smem); writes h16b bank ----------------
__global__ void lin_gene_kernel(const float* __restrict__ agg,
                                const float* __restrict__ h,
                                __half* __restrict__ h16b,
                                const float* __restrict__ convWl,
                                const float* __restrict__ convbl,
                                const float* __restrict__ convWr,
                                const float* __restrict__ gamma,
                                const float* __restrict__ beta) {
    extern __shared__ float sm[];
    float* sWa = sm;
    float* sWb = sm + 4096;
    float* sWc = sm + 8192;
    float* sTa = sm + 12288;
    float* sTb = sm + 16384;
    float* sTc = sm + 20480;

    const float* Wl1 = convWl + (size_t)1 * HID * HID;
    const float* Wl3 = convWl + (size_t)3 * HID * HID;
    const float* Wr1 = convWr + (size_t)1 * HID * HID;
    const float* Wr3 = convWr + (size_t)3 * HID * HID;
    for (int i = threadIdx.x; i < 4096; i += 256) {
        sWa[i] = Wl1[i];
        sWb[i] = Wl3[i];
        sWc[i] = Wr1[i] + Wr3[i];
    }
    int tx = threadIdx.x & 15;
    int ty = threadIdx.x >> 4;
    int j0 = tx * 4;
    int nb = ty * 4;
    float4 b1 = *(const float4*)(convbl + HID + j0);
    float4 b3 = *(const float4*)(convbl + 3 * HID + j0);
    float4 bias = make_float4(b1.x + b3.x, b1.y + b3.y, b1.z + b3.z, b1.w + b3.w);

    int n0 = blockIdx.x * 64;
    for (int i = threadIdx.x; i < 64 * 16; i += 256) {
        int nn = i >> 4, q = i & 15;
        int n = n0 + nn;
        float4 v1 = make_float4(0.f, 0.f, 0.f, 0.f), v3 = v1, vr = v1;
        if (n < NG) {
            v1 = ((const float4*)(agg + (size_t)(A1 + n) * HID))[q];
            v3 = ((const float4*)(agg + (size_t)(A3 + n) * HID))[q];
            vr = ((const float4*)(h + (size_t)n * HID))[q];
        }
        *(float4*)&sTa[nn * 64 + q * 4] = v1;
        *(float4*)&sTb[nn * 64 + q * 4] = v3;
        *(float4*)&sTc[nn * 64 + q * 4] = vr;
    }
    __syncthreads();

    float acc[4][4];
#pragma unroll
    for (int i = 0; i < 4; i++) {
        acc[i][0] = bias.x; acc[i][1] = bias.y; acc[i][2] = bias.z; acc[i][3] = bias.w;
    }
#pragma unroll 4
    for (int k = 0; k < 64; k++) {
        float4 wa = *(const float4*)&sWa[k * 64 + j0];
        float4 wb = *(const float4*)&sWb[k * 64 + j0];
        float4 wc = *(const float4*)&sWc[k * 64 + j0];
#pragma unroll
        for (int i = 0; i < 4; i++) {
            float a1 = sTa[(nb + i) * 64 + k];
            float a3 = sTb[(nb + i) * 64 + k];
            float r  = sTc[(nb + i) * 64 + k];
            acc[i][0] += a1 * wa.x + a3 * wb.x + r * wc.x;
            acc[i][1] += a1 * wa.y + a3 * wb.y + r * wc.y;
            acc[i][2] += a1 * wa.z + a3 * wb.z + r * wc.z;
            acc[i][3] += a1 * wa.w + a3 * wb.w + r * wc.w;
        }
    }

    float4 gm = *(const float4*)(gamma + j0);
    float4 bt = *(const float4*)(beta + j0);
#pragma unroll
    for (int i = 0; i < 4; i++) {
        int n = n0 + nb + i;
        float e0 = acc[i][0] + sTc[(nb + i) * 64 + j0];
        float e1 = acc[i][1] + sTc[(nb + i) * 64 + j0 + 1];
        float e2 = acc[i][2] + sTc[(nb + i) * 64 + j0 + 2];
        float e3 = acc[i][3] + sTc[(nb + i) * 64 + j0 + 3];
        float s = e0 + e1 + e2 + e3;
#pragma unroll
        for (int o = 1; o < 16; o <<= 1) s += __shfl_xor_sync(FULL, s, o);
        float mean = s * (1.f / 64.f);
        float d0 = e0 - mean, d1 = e1 - mean, d2 = e2 - mean, d3 = e3 - mean;
        float v = d0 * d0 + d1 * d1 + d2 * d2 + d3 * d3;
#pragma unroll
        for (int o = 1; o < 16; o <<= 1) v += __shfl_xor_sync(FULL, v, o);
        float rstd = rsqrtf(v * (1.f / 64.f) + 1e-5f);
        if (n < NG) {
            __half2* hp = (__half2*)(h16b + (size_t)n * HID + j0);
            hp[0] = __floats2half2_rn(elu1(d0 * rstd * gm.x + bt.x),
                                      elu1(d1 * rstd * gm.y + bt.y));
            hp[1] = __floats2half2_rn(elu1(d2 * rstd * gm.z + bt.z),
                                      elu1(d3 * rstd * gm.w + bt.w));
        }
    }
}

// ---------------- host launcher ----------------
static inline int cdiv(long long a, long long b) { return (int)((a + b - 1) / b); }

extern "C" void kernel_launch(void* const* d_in, const int* in_sizes, int n_in,
                              void* d_out, int out_size) {
    const float* x_gene = (const float*)d_in[0];
    const float* x_pat  = (const float*)d_in[1];
    const float* x_grp  = (const float*)d_in[2];
    const int* src0 = (const int*)d_in[3];
    const int* dst0 = (const int*)d_in[4];
    const int* src1 = (const int*)d_in[5];
    const int* dst1 = (const int*)d_in[6];
    // d_in[7], d_in[8]: src2/dst2 — dead for the output
    const int* src3 = (const int*)d_in[9];
    const int* dst3 = (const int*)d_in[10];
    const float* encGW = (const float*)d_in[11];
    const float* encGb = (const float*)d_in[12];
    const float* encPW = (const float*)d_in[13];
    const float* encPb = (const float*)d_in[14];
    const float* encMW = (const float*)d_in[15];
    const float* encMb = (const float*)d_in[16];
    const float* convWl = (const float*)d_in[17];   // [2,4,64,64]
    const float* convbl = (const float*)d_in[18];   // [2,4,64]
    const float* convWr = (const float*)d_in[19];   // [2,4,64,64]
    const float* lnG = (const float*)d_in[20];      // [2,3,64]
    const float* lnB = (const float*)d_in[21];
    const float* coxW1 = (const float*)d_in[22];
    const float* coxb1 = (const float*)d_in[23];
    const float* coxW2 = (const float*)d_in[24];
    const float* coxb2 = (const float*)d_in[25];
    float* out = (float*)d_out;

    const int E = in_sizes[3];

    float *hbuf, *aggbuf;
    __half *h16buf, *h16b;
    cudaGetSymbolAddress((void**)&hbuf,   g_h);
    cudaGetSymbolAddress((void**)&h16buf, g_h16);
    cudaGetSymbolAddress((void**)&h16b,   g_h16b);
    cudaGetSymbolAddress((void**)&aggbuf, g_agg);
    float* agg2 = aggbuf + (size_t)NSEG1 * HID;   // layer-2 e0 bank

    static const int PAT_SMEM  = 4 * 4096 * (int)sizeof(float);   // 64 KB
    static const int GENE_SMEM = 6 * 4096 * (int)sizeof(float);   // 96 KB
    cudaFuncSetAttribute(lin_pat_kernel,
                         cudaFuncAttributeMaxDynamicSharedMemorySize, PAT_SMEM);
    cudaFuncSetAttribute(lin_gene_kernel,
                         cudaFuncAttributeMaxDynamicSharedMemorySize, GENE_SMEM);

    // one-time host objects (created on the correctness call, outside capture)
    static cudaStream_t s_side = nullptr;
    static cudaEvent_t ev_fork = nullptr, ev_join = nullptr;
    if (s_side == nullptr) {
        cudaStreamCreateWithFlags(&s_side, cudaStreamNonBlocking);
        cudaEventCreateWithFlags(&ev_fork, cudaEventDisableTiming);
        cudaEventCreateWithFlags(&ev_join, cudaEventDisableTiming);
    }

    // [1] merged encoders + degree counts (rank-storing)
    int cntB = cdiv(3LL * E, 256);
    enc_count_kernel<<<ENCB + cntB, 256>>>(
        x_gene, x_pat, x_grp, encGW, encGb, encPW, encPb, encMW, encMb,
        hbuf, h16buf, dst0, dst1, dst3, E);

    // [2-4] scan + atomic-free fill
    scanA_kernel<<<NBTOT, 256>>>();
    scanC_kernel<<<NBTOT, 256>>>(E);
    fill_all_kernel<<<cdiv(3LL * E, 256), 256>>>(src0, dst0, src1, dst1, src3, dst3, E);

    // fork after fill:
    //   side: pull_e13 -> gene linear (writes h16b) -> layer-2 pull e0 (from h16b)
    //   main: pull_e0 -> patient L1 linear
    cudaEventRecord(ev_fork, 0);
    cudaStreamWaitEvent(s_side, ev_fork, 0);

    pull_all_kernel<<<cdiv((long long)(2 * NG) * 32, 256), 256, 0, s_side>>>(
        h16buf, aggbuf + (size_t)A1 * HID, A1, 2 * NG);
    lin_gene_kernel<<<T1, 256, GENE_SMEM, s_side>>>(
        aggbuf, hbuf, h16b, convWl, convbl, convWr, lnG, lnB);
    pull_all_kernel<<<cdiv((long long)NP * 32, 256), 256, 0, s_side>>>(
        h16b, agg2, 0, NP);
    cudaEventRecord(ev_join, s_side);

    pull_all_kernel<<<cdiv((long long)NP * 32, 256), 256>>>(
        h16buf, aggbuf, 0, NP);
    lin_pat_kernel<<<T0, 256, PAT_SMEM>>>(
        aggbuf, hbuf, convWl, convbl, convWr, lnG + HID, lnB + HID,
        coxW1, coxb1, coxW2, coxb2, out, 0);

    // join, then layer-2 patient linear + cox
    cudaStreamWaitEvent(0, ev_join, 0);
    lin_pat_kernel<<<T0, 256, PAT_SMEM>>>(
        agg2, hbuf,
        convWl + (size_t)4 * HID * HID,
        convbl + (size_t)4 * HID,
        convWr + (size_t)4 * HID * HID,
        lnG + (size_t)3 * HID + HID,
        lnB + (size_t)3 * HID + HID,
        coxW1, coxb1, coxW2, coxb2, out, 1);
}